// round 3
// baseline (speedup 1.0000x reference)
#include <cuda_runtime.h>
#include <cuda_bf16.h>
#include <mma.h>
#include <math.h>

using namespace nvcuda;

#define BSZ     8
#define QL      16
#define TOK     128
#define DIM     4096
#define NKV     8
#define HD      128
#define MAXSEQ  4096
#define STARTP  4080
#define KVLEN   4096
#define QKV_N   6144
#define NBG     64
#define NSPLIT  4
#define KVSPLIT 1024          // kv positions per split
#define LT      64            // kv tile inside flash

// ---------------- scratch ----------------------------------------------------
__device__ float g_qkv[TOK * QKV_N];                 // raw qkv (no bias)
__device__ float g_pvp[NSPLIT * NBG * 64 * HD];      // 8 MB unnormalized O partials
__device__ float g_rsum[NSPLIT * NBG * 64];          // row sums (denominators)
__device__ float g_att[TOK * DIM];                   // attention output (token layout)

// ---------------- k=16 wmma step: As[64][LDA] row, Bs[16][LDB] row ------------
template<int LDA, int LDB>
__device__ __forceinline__ void mma_k16(
    const float* __restrict__ As, const float* __restrict__ Bs,
    wmma::fragment<wmma::accumulator, 16, 16, 8, float> (&acc)[2][2],
    int wr, int wc)
{
#pragma unroll
    for (int kk = 0; kk < 16; kk += 8) {
        wmma::fragment<wmma::matrix_a, 16, 16, 8, wmma::precision::tf32, wmma::row_major> a[2];
        wmma::fragment<wmma::matrix_b, 16, 16, 8, wmma::precision::tf32, wmma::row_major> b[2];
#pragma unroll
        for (int i = 0; i < 2; i++) {
            wmma::load_matrix_sync(a[i], As + (wr * 32 + i * 16) * LDA + kk, LDA);
#pragma unroll
            for (int t = 0; t < a[i].num_elements; t++)
                a[i].x[t] = wmma::__float_to_tf32(a[i].x[t]);
        }
#pragma unroll
        for (int j = 0; j < 2; j++) {
            wmma::load_matrix_sync(b[j], Bs + kk * LDB + wc * 32 + j * 16, LDB);
#pragma unroll
            for (int t = 0; t < b[j].num_elements; t++)
                b[j].x[t] = wmma::__float_to_tf32(b[j].x[t]);
        }
#pragma unroll
        for (int i = 0; i < 2; i++)
#pragma unroll
            for (int j = 0; j < 2; j++)
                wmma::mma_sync(acc[i][j], a[i], b[j], acc[i][j]);
    }
}

// ---------------- kernel 1: QKV GEMM, double-buffered -------------------------
// grid (48, 2), 256 thr. Tile 64(m) x 128(n), K=4096 in 256 chunks of 16.
__global__ void __launch_bounds__(256) qkv_kernel(
    const float* __restrict__ x,
    const float* __restrict__ Wq, const float* __restrict__ Wk,
    const float* __restrict__ Wv)
{
    __shared__ float As[2][64 * 20];
    __shared__ float Bs[2][16 * 132];

    const int n0 = blockIdx.x * 128;
    const int m0 = blockIdx.y * 64;
    const float* B; int ldb, col;
    if (n0 < 4096)      { B = Wq; ldb = 4096; col = n0; }
    else if (n0 < 5120) { B = Wk; ldb = 1024; col = n0 - 4096; }
    else                { B = Wv; ldb = 1024; col = n0 - 5120; }

    const int tid = threadIdx.x;
    const int wid = tid >> 5, wr = wid >> 2, wc = wid & 3;

    const int am = tid >> 2, ak = (tid & 3) << 2;     // A: 64x16 = 256 f4
    const int bkk = tid >> 5, bn = (tid & 31) << 2;   // B: 16x128 = 512 f4 (2/thr)
    const float* aptr = x + (size_t)(m0 + am) * DIM + ak;
    const float* bptr = B + (size_t)bkk * ldb + col + bn;

    wmma::fragment<wmma::accumulator, 16, 16, 8, float> acc[2][2];
#pragma unroll
    for (int i = 0; i < 2; i++)
#pragma unroll
        for (int j = 0; j < 2; j++) wmma::fill_fragment(acc[i][j], 0.0f);

    float4 ra  = *(const float4*)(aptr);
    float4 rb0 = *(const float4*)(bptr);
    float4 rb1 = *(const float4*)(bptr + (size_t)8 * ldb);
    *(float4*)(&As[0][am * 20 + ak]) = ra;
    *(float4*)(&Bs[0][bkk * 132 + bn]) = rb0;
    *(float4*)(&Bs[0][(bkk + 8) * 132 + bn]) = rb1;
    __syncthreads();

    const int NT = DIM / 16;
    for (int t = 0; t < NT; t++) {
        int cur = t & 1;
        if (t + 1 < NT) {
            ra  = *(const float4*)(aptr + (t + 1) * 16);
            rb0 = *(const float4*)(bptr + (size_t)(t + 1) * 16 * ldb);
            rb1 = *(const float4*)(bptr + (size_t)((t + 1) * 16 + 8) * ldb);
        }
        mma_k16<20, 132>(As[cur], Bs[cur], acc, wr, wc);
        if (t + 1 < NT) {
            *(float4*)(&As[1 - cur][am * 20 + ak]) = ra;
            *(float4*)(&Bs[1 - cur][bkk * 132 + bn]) = rb0;
            *(float4*)(&Bs[1 - cur][(bkk + 8) * 132 + bn]) = rb1;
        }
        __syncthreads();
    }
#pragma unroll
    for (int i = 0; i < 2; i++)
#pragma unroll
        for (int j = 0; j < 2; j++)
            wmma::store_matrix_sync(
                g_qkv + (size_t)(m0 + wr * 32 + i * 16) * QKV_N + n0 + wc * 32 + j * 16,
                acc[i][j], QKV_N, wmma::mem_row_major);
}

// ---------------- kernel 2: flash attention (no-max softmax, split-kv) --------
// grid (NSPLIT, NBG), 256 thr, dynamic smem.
// Computes unnormalized O_partial = sum_l exp(q.k*scale) * v and row sums.
#define SMEM_FLASH ((64*132 + 64*136 + 64*72 + 64 + 256) * 4)

__global__ void __launch_bounds__(256) flash_kernel(
    const float* __restrict__ k_cache, const float* __restrict__ v_cache,
    const float* __restrict__ bq, const float* __restrict__ bk,
    const float* __restrict__ bv)
{
    extern __shared__ float sm[];
    float* Qs     = sm;                  // [64][132] biased, scaled Q
    float* KVs    = Qs + 64 * 132;       // [64][136] K tile then V tile
    float* Ss     = KVs + 64 * 136;      // [64][72]  scores tile
    float* rowsum = Ss + 64 * 72;        // [64]
    float* tmp    = rowsum + 64;         // [4][64]

    const int split = blockIdx.x;
    const int bg = blockIdx.y, b = bg >> 3, g = bg & 7;
    const int tid = threadIdx.x, wid = tid >> 5;
    const int wr2 = wid >> 2, wc4 = wid & 3;     // S partition: 32-row x 16-col
    const int wr4 = wid >> 1, wc1 = wid & 1;     // PV partition: 16-row x 64-col
    const float scale = 0.08838834764831845f;

    // Q: 64 rows x 128 d, with bias + scale
#pragma unroll
    for (int i = 0; i < 8; i++) {
        int idx = tid + i * 256;
        int m = idx >> 5, d4 = (idx & 31) << 2;
        int r = m >> 4, s = m & 15;
        int hcol = (g * 4 + r) * HD + d4;
        float4 q = *(const float4*)(g_qkv + (size_t)(b * 16 + s) * QKV_N + hcol);
        float4 bb = *(const float4*)(bq + hcol);
        float4 o;
        o.x = (q.x + bb.x) * scale; o.y = (q.y + bb.y) * scale;
        o.z = (q.z + bb.z) * scale; o.w = (q.w + bb.w) * scale;
        *(float4*)(Qs + m * 132 + d4) = o;
    }
    if (tid < 64) rowsum[tid] = 0.f;
    __syncthreads();

    wmma::fragment<wmma::accumulator, 16, 16, 8, float> acc_o[4];
#pragma unroll
    for (int j = 0; j < 4; j++) wmma::fill_fragment(acc_o[j], 0.0f);

    const int row = tid & 63, qq = tid >> 6;   // exp-phase mapping

    for (int t = 0; t < KVSPLIT / LT; t++) {
        const int l0 = split * KVSPLIT + t * LT;

        // K tile: 64 l x 128 d
#pragma unroll
        for (int i = 0; i < 8; i++) {
            int idx = tid + i * 256;
            int l = idx >> 5, d4 = (idx & 31) << 2;
            int lg = l0 + l;
            float4 kv;
            if (lg >= STARTP) {
                kv = *(const float4*)(g_qkv + (size_t)(b * 16 + (lg - STARTP)) * QKV_N
                                      + 4096 + g * HD + d4);
                float4 bb = *(const float4*)(bk + g * HD + d4);
                kv.x += bb.x; kv.y += bb.y; kv.z += bb.z; kv.w += bb.w;
            } else {
                kv = *(const float4*)(k_cache + (((size_t)b * MAXSEQ + lg) * NKV + g) * HD + d4);
            }
            *(float4*)(KVs + l * 136 + d4) = kv;
        }
        __syncthreads();

        // S = Q @ K^T (64x64, k=128)
        wmma::fragment<wmma::accumulator, 16, 16, 8, float> acc_s[2];
        wmma::fill_fragment(acc_s[0], 0.0f);
        wmma::fill_fragment(acc_s[1], 0.0f);
#pragma unroll
        for (int kk = 0; kk < HD; kk += 8) {
            wmma::fragment<wmma::matrix_a, 16, 16, 8, wmma::precision::tf32, wmma::row_major> a[2];
            wmma::fragment<wmma::matrix_b, 16, 16, 8, wmma::precision::tf32, wmma::col_major> bfr;
#pragma unroll
            for (int i = 0; i < 2; i++) {
                wmma::load_matrix_sync(a[i], Qs + (wr2 * 32 + i * 16) * 132 + kk, 132);
#pragma unroll
                for (int e = 0; e < a[i].num_elements; e++)
                    a[i].x[e] = wmma::__float_to_tf32(a[i].x[e]);
            }
            wmma::load_matrix_sync(bfr, KVs + (wc4 * 16) * 136 + kk, 136);
#pragma unroll
            for (int e = 0; e < bfr.num_elements; e++)
                bfr.x[e] = wmma::__float_to_tf32(bfr.x[e]);
#pragma unroll
            for (int i = 0; i < 2; i++)
                wmma::mma_sync(acc_s[i], a[i], bfr, acc_s[i]);
        }
#pragma unroll
        for (int i = 0; i < 2; i++)
            wmma::store_matrix_sync(Ss + (wr2 * 32 + i * 16) * 72 + wc4 * 16,
                                    acc_s[i], 72, wmma::mem_row_major);
        __syncthreads();

        // exp + partial row sums; concurrently load V tile into KVs
        {
            float part = 0.f;
            float* sp = Ss + row * 72 + qq * 16;
#pragma unroll
            for (int j = 0; j < 16; j++) {
                float e = __expf(sp[j]);
                sp[j] = e;
                part += e;
            }
            tmp[qq * 64 + row] = part;
        }
#pragma unroll
        for (int i = 0; i < 8; i++) {
            int idx = tid + i * 256;
            int l = idx >> 5, d4 = (idx & 31) << 2;
            int lg = l0 + l;
            float4 v;
            if (lg >= STARTP) {
                v = *(const float4*)(g_qkv + (size_t)(b * 16 + (lg - STARTP)) * QKV_N
                                     + 5120 + g * HD + d4);
                float4 bb = *(const float4*)(bv + g * HD + d4);
                v.x += bb.x; v.y += bb.y; v.z += bb.z; v.w += bb.w;
            } else {
                v = *(const float4*)(v_cache + (((size_t)b * MAXSEQ + lg) * NKV + g) * HD + d4);
            }
            *(float4*)(KVs + l * 136 + d4) = v;
        }
        __syncthreads();

        if (tid < 64)
            rowsum[tid] += tmp[tid] + tmp[64 + tid] + tmp[128 + tid] + tmp[192 + tid];

        // O += P @ V (64x128, k=64)
#pragma unroll
        for (int kk = 0; kk < LT; kk += 8) {
            wmma::fragment<wmma::matrix_a, 16, 16, 8, wmma::precision::tf32, wmma::row_major> a;
            wmma::load_matrix_sync(a, Ss + (wr4 * 16) * 72 + kk, 72);
#pragma unroll
            for (int e = 0; e < a.num_elements; e++)
                a.x[e] = wmma::__float_to_tf32(a.x[e]);
#pragma unroll
            for (int j = 0; j < 4; j++) {
                wmma::fragment<wmma::matrix_b, 16, 16, 8, wmma::precision::tf32, wmma::row_major> bfr;
                wmma::load_matrix_sync(bfr, KVs + kk * 136 + wc1 * 64 + j * 16, 136);
#pragma unroll
                for (int e = 0; e < bfr.num_elements; e++)
                    bfr.x[e] = wmma::__float_to_tf32(bfr.x[e]);
                wmma::mma_sync(acc_o[j], a, bfr, acc_o[j]);
            }
        }
        __syncthreads();
    }

    // store unnormalized O partial + row sums
#pragma unroll
    for (int j = 0; j < 4; j++)
        wmma::store_matrix_sync(
            g_pvp + ((size_t)(split * NBG + bg) * 64 + wr4 * 16) * HD + wc1 * 64 + j * 16,
            acc_o[j], HD, wmma::mem_row_major);
    if (tid < 64)
        g_rsum[(size_t)(split * NBG + bg) * 64 + tid] = rowsum[tid];
}

// ---------------- kernel 3: combine splits, normalize, remap ------------------
__global__ void flash_combine_kernel()
{
    int t = blockIdx.x * 256 + threadIdx.x;     // 131072 threads
    int rowg = t >> 5;                           // bg*64 + qr  (0..4095)
    int c4 = (t & 31) << 2;
    float4 s = make_float4(0.f, 0.f, 0.f, 0.f);
    float den = 0.f;
#pragma unroll
    for (int sp = 0; sp < NSPLIT; sp++) {
        float4 v = *(const float4*)(g_pvp + ((size_t)sp * NBG * 64 + rowg) * HD + c4);
        s.x += v.x; s.y += v.y; s.z += v.z; s.w += v.w;
        den += g_rsum[(size_t)sp * NBG * 64 + rowg];
    }
    float inv = 1.f / den;
    s.x *= inv; s.y *= inv; s.z *= inv; s.w *= inv;
    int bg = rowg >> 6, qr = rowg & 63;
    int b = bg >> 3, g = bg & 7, r = qr >> 4, sq = qr & 15;
    *(float4*)(g_att + (size_t)(b * 16 + sq) * DIM + (g * 4 + r) * HD + c4) = s;
}

// ---------------- kernel 4: O projection, double-buffered ---------------------
__global__ void __launch_bounds__(256) o_kernel(
    const float* __restrict__ Wo, float* __restrict__ out)
{
    __shared__ float As[2][64 * 20];
    __shared__ float Bs[2][16 * 132];

    const int n0 = blockIdx.x * 128;
    const int m0 = blockIdx.y * 64;
    const int tid = threadIdx.x;
    const int wid = tid >> 5, wr = wid >> 2, wc = wid & 3;

    const int am = tid >> 2, ak = (tid & 3) << 2;
    const int bkk = tid >> 5, bn = (tid & 31) << 2;
    const float* aptr = g_att + (size_t)(m0 + am) * DIM + ak;
    const float* bptr = Wo + (size_t)bkk * DIM + n0 + bn;

    wmma::fragment<wmma::accumulator, 16, 16, 8, float> acc[2][2];
#pragma unroll
    for (int i = 0; i < 2; i++)
#pragma unroll
        for (int j = 0; j < 2; j++) wmma::fill_fragment(acc[i][j], 0.0f);

    float4 ra  = *(const float4*)(aptr);
    float4 rb0 = *(const float4*)(bptr);
    float4 rb1 = *(const float4*)(bptr + (size_t)8 * DIM);
    *(float4*)(&As[0][am * 20 + ak]) = ra;
    *(float4*)(&Bs[0][bkk * 132 + bn]) = rb0;
    *(float4*)(&Bs[0][(bkk + 8) * 132 + bn]) = rb1;
    __syncthreads();

    const int NT = DIM / 16;
    for (int t = 0; t < NT; t++) {
        int cur = t & 1;
        if (t + 1 < NT) {
            ra  = *(const float4*)(aptr + (t + 1) * 16);
            rb0 = *(const float4*)(bptr + (size_t)(t + 1) * 16 * DIM);
            rb1 = *(const float4*)(bptr + (size_t)((t + 1) * 16 + 8) * DIM);
        }
        mma_k16<20, 132>(As[cur], Bs[cur], acc, wr, wc);
        if (t + 1 < NT) {
            *(float4*)(&As[1 - cur][am * 20 + ak]) = ra;
            *(float4*)(&Bs[1 - cur][bkk * 132 + bn]) = rb0;
            *(float4*)(&Bs[1 - cur][(bkk + 8) * 132 + bn]) = rb1;
        }
        __syncthreads();
    }
#pragma unroll
    for (int i = 0; i < 2; i++)
#pragma unroll
        for (int j = 0; j < 2; j++)
            wmma::store_matrix_sync(
                out + (size_t)(m0 + wr * 32 + i * 16) * DIM + n0 + wc * 32 + j * 16,
                acc[i][j], DIM, wmma::mem_row_major);
}

// ---------------- kernel 5: add output bias ------------------------------------
__global__ void bias_kernel(float* __restrict__ out, const float* __restrict__ bo)
{
    int t = blockIdx.x * 256 + threadIdx.x;
    int i4 = t * 4;
    int n = i4 & (DIM - 1);
    float4 v = *(const float4*)(out + i4);
    float4 bb = *(const float4*)(bo + n);
    v.x += bb.x; v.y += bb.y; v.z += bb.z; v.w += bb.w;
    *(float4*)(out + i4) = v;
}

// ---------------- launch ---------------------------------------------------------
extern "C" void kernel_launch(void* const* d_in, const int* in_sizes, int n_in,
                              void* d_out, int out_size)
{
    const float* x  = (const float*)d_in[0];
    const float* kc = (const float*)d_in[1];
    const float* vc = (const float*)d_in[2];
    const float* Wq = (const float*)d_in[3];  const float* bq = (const float*)d_in[4];
    const float* Wk = (const float*)d_in[5];  const float* bk = (const float*)d_in[6];
    const float* Wv = (const float*)d_in[7];  const float* bv = (const float*)d_in[8];
    const float* Wo = (const float*)d_in[9];  const float* bo = (const float*)d_in[10];
    float* out = (float*)d_out;

    cudaFuncSetAttribute(flash_kernel,
                         cudaFuncAttributeMaxDynamicSharedMemorySize, SMEM_FLASH);

    qkv_kernel<<<dim3(48, 2), 256>>>(x, Wq, Wk, Wv);
    flash_kernel<<<dim3(NSPLIT, NBG), 256, SMEM_FLASH>>>(kc, vc, bq, bk, bv);
    flash_combine_kernel<<<512, 256>>>();
    o_kernel<<<dim3(32, 2), 256>>>(Wo, out);
    bias_kernel<<<512, 256>>>(out, bo);
}

// round 4
// speedup vs baseline: 1.6169x; 1.6169x over previous
#include <cuda_runtime.h>
#include <cuda_bf16.h>
#include <mma.h>
#include <math.h>

using namespace nvcuda;

#define BSZ     8
#define QL      16
#define TOK     128
#define DIM     4096
#define NKV     8
#define HD      128
#define MAXSEQ  4096
#define STARTP  4080
#define KVLEN   4096
#define QKV_N   6144
#define NBG     64
#define NSPLIT  8
#define KVSPLIT 512
#define LT      64
#define SPLITQ  4
#define SPLITO  4

__device__ float g_qkv[TOK * QKV_N];
__device__ float g_qkvp[SPLITQ * TOK * QKV_N];   // 12.6 MB
__device__ float g_op[SPLITO * TOK * DIM];       // 8 MB
__device__ float g_pvp[NSPLIT * NBG * 64 * HD];  // 16 MB
__device__ float g_rsum[NSPLIT * NBG * 64];
__device__ float g_att[TOK * DIM];

__device__ __forceinline__ float tf32r(float x) { return wmma::__float_to_tf32(x); }

typedef wmma::fragment<wmma::accumulator, 16, 16, 8, float> FragC;
typedef wmma::fragment<wmma::matrix_a, 16, 16, 8, wmma::precision::tf32, wmma::row_major> FragA;
typedef wmma::fragment<wmma::matrix_b, 16, 16, 8, wmma::precision::tf32, wmma::row_major> FragB;
typedef wmma::fragment<wmma::matrix_b, 16, 16, 8, wmma::precision::tf32, wmma::col_major> FragBT;

// k=32 step on pre-rounded smem. As[64][LDA] row-major, Bs[32][LDB] row-major.
template<int LDA, int LDB>
__device__ __forceinline__ void mma32(
    const float* __restrict__ As, const float* __restrict__ Bs,
    FragC (&acc)[2][2], int wr, int wc)
{
#pragma unroll
    for (int kk = 0; kk < 32; kk += 8) {
        FragA a[2]; FragB b[2];
#pragma unroll
        for (int i = 0; i < 2; i++)
            wmma::load_matrix_sync(a[i], As + (wr * 32 + i * 16) * LDA + kk, LDA);
#pragma unroll
        for (int j = 0; j < 2; j++)
            wmma::load_matrix_sync(b[j], Bs + kk * LDB + wc * 32 + j * 16, LDB);
#pragma unroll
        for (int i = 0; i < 2; i++)
#pragma unroll
            for (int j = 0; j < 2; j++)
                wmma::mma_sync(acc[i][j], a[i], b[j], acc[i][j]);
    }
}

// ---------------- split-K 64x128 GEMM body (shared by QKV and O) --------------
// A row-major [64 x *] at (Arow, kbase), B row-major [* x 128] at (kbase, Bcol).
// 32 chunks of k=32, double-buffered, tf32-rounded at staging.
#define GEMM_BODY(Abase, LDAG, Bbase, LDBG, CPART, LDC)                            \
    __shared__ float As[2][64 * 36];                                               \
    __shared__ float Bs[2][32 * 132];                                              \
    const int tid = threadIdx.x;                                                   \
    const int wid = tid >> 5, wr = wid >> 2, wc = wid & 3;                         \
    int amr[2], akc[2], bkr[4], bnc[4];                                            \
    _Pragma("unroll")                                                              \
    for (int i = 0; i < 2; i++) { int idx = tid + i * 256; amr[i] = idx >> 3; akc[i] = (idx & 7) << 2; } \
    _Pragma("unroll")                                                              \
    for (int i = 0; i < 4; i++) { int idx = tid + i * 256; bkr[i] = idx >> 5; bnc[i] = (idx & 31) << 2; } \
    FragC acc[2][2];                                                               \
    _Pragma("unroll")                                                              \
    for (int i = 0; i < 2; i++)                                                    \
        _Pragma("unroll")                                                          \
        for (int j = 0; j < 2; j++) wmma::fill_fragment(acc[i][j], 0.0f);          \
    float4 ra[2], rb[4];                                                           \
    _Pragma("unroll")                                                              \
    for (int i = 0; i < 2; i++)                                                    \
        ra[i] = *(const float4*)((Abase) + (size_t)amr[i] * (LDAG) + akc[i]);      \
    _Pragma("unroll")                                                              \
    for (int i = 0; i < 4; i++)                                                    \
        rb[i] = *(const float4*)((Bbase) + (size_t)bkr[i] * (LDBG) + bnc[i]);      \
    _Pragma("unroll")                                                              \
    for (int i = 0; i < 2; i++) {                                                  \
        float4 c = ra[i];                                                          \
        c.x = tf32r(c.x); c.y = tf32r(c.y); c.z = tf32r(c.z); c.w = tf32r(c.w);    \
        *(float4*)(&As[0][amr[i] * 36 + akc[i]]) = c;                              \
    }                                                                              \
    _Pragma("unroll")                                                              \
    for (int i = 0; i < 4; i++) {                                                  \
        float4 c = rb[i];                                                          \
        c.x = tf32r(c.x); c.y = tf32r(c.y); c.z = tf32r(c.z); c.w = tf32r(c.w);    \
        *(float4*)(&Bs[0][bkr[i] * 132 + bnc[i]]) = c;                             \
    }                                                                              \
    __syncthreads();                                                               \
    for (int t = 0; t < 32; t++) {                                                 \
        int cur = t & 1;                                                           \
        if (t + 1 < 32) {                                                          \
            _Pragma("unroll")                                                      \
            for (int i = 0; i < 2; i++)                                            \
                ra[i] = *(const float4*)((Abase) + (size_t)amr[i] * (LDAG) + (t + 1) * 32 + akc[i]); \
            _Pragma("unroll")                                                      \
            for (int i = 0; i < 4; i++)                                            \
                rb[i] = *(const float4*)((Bbase) + (size_t)((t + 1) * 32 + bkr[i]) * (LDBG) + bnc[i]); \
        }                                                                          \
        mma32<36, 132>(As[cur], Bs[cur], acc, wr, wc);                             \
        if (t + 1 < 32) {                                                          \
            _Pragma("unroll")                                                      \
            for (int i = 0; i < 2; i++) {                                          \
                float4 c = ra[i];                                                  \
                c.x = tf32r(c.x); c.y = tf32r(c.y); c.z = tf32r(c.z); c.w = tf32r(c.w); \
                *(float4*)(&As[1 - cur][amr[i] * 36 + akc[i]]) = c;                \
            }                                                                      \
            _Pragma("unroll")                                                      \
            for (int i = 0; i < 4; i++) {                                          \
                float4 c = rb[i];                                                  \
                c.x = tf32r(c.x); c.y = tf32r(c.y); c.z = tf32r(c.z); c.w = tf32r(c.w); \
                *(float4*)(&Bs[1 - cur][bkr[i] * 132 + bnc[i]]) = c;               \
            }                                                                      \
        }                                                                          \
        __syncthreads();                                                           \
    }                                                                              \
    _Pragma("unroll")                                                              \
    for (int i = 0; i < 2; i++)                                                    \
        _Pragma("unroll")                                                          \
        for (int j = 0; j < 2; j++)                                                \
            wmma::store_matrix_sync((CPART) + (size_t)(wr * 32 + i * 16) * (LDC) + wc * 32 + j * 16, \
                                    acc[i][j], (LDC), wmma::mem_row_major);

// ---------------- kernel 1: QKV GEMM split-K ----------------------------------
__global__ void __launch_bounds__(256) qkv_kernel(
    const float* __restrict__ x,
    const float* __restrict__ Wq, const float* __restrict__ Wk,
    const float* __restrict__ Wv)
{
    const int n0 = blockIdx.x * 128;
    const int kb = blockIdx.y * 1024;
    const int m0 = blockIdx.z * 64;
    const float* B; int ldb, col;
    if (n0 < 4096)      { B = Wq; ldb = 4096; col = n0; }
    else if (n0 < 5120) { B = Wk; ldb = 1024; col = n0 - 4096; }
    else                { B = Wv; ldb = 1024; col = n0 - 5120; }

    const float* Abase = x + (size_t)m0 * DIM + kb;
    const float* Bbase = B + (size_t)kb * ldb + col;
    float* Cpart = g_qkvp + ((size_t)blockIdx.y * TOK + m0) * QKV_N + n0;
    GEMM_BODY(Abase, DIM, Bbase, ldb, Cpart, QKV_N)
}

__global__ void qkv_reduce_kernel()
{
    int i4 = (blockIdx.x * 256 + threadIdx.x) * 4;    // TOK*QKV_N/4 threads
    float4 s = make_float4(0.f, 0.f, 0.f, 0.f);
#pragma unroll
    for (int sp = 0; sp < SPLITQ; sp++) {
        float4 v = *(const float4*)(g_qkvp + (size_t)sp * TOK * QKV_N + i4);
        s.x += v.x; s.y += v.y; s.z += v.z; s.w += v.w;
    }
    *(float4*)(g_qkv + i4) = s;
}

// ---------------- kernel 2: flash attention (no-max softmax, split-kv) --------
#define SMEM_FLASH ((64*132 + 64*136 + 64*72 + 64 + 256) * 4)

__global__ void __launch_bounds__(256) flash_kernel(
    const float* __restrict__ k_cache, const float* __restrict__ v_cache,
    const float* __restrict__ bq, const float* __restrict__ bk,
    const float* __restrict__ bv)
{
    extern __shared__ float sm[];
    float* Qs     = sm;                  // [64][132]
    float* KVs    = Qs + 64 * 132;       // [64][136]
    float* Ss     = KVs + 64 * 136;      // [64][72]
    float* rowsum = Ss + 64 * 72;        // [64]
    float* tmp    = rowsum + 64;         // [4][64]

    const int split = blockIdx.x;
    const int bg = blockIdx.y, b = bg >> 3, g = bg & 7;
    const int tid = threadIdx.x, wid = tid >> 5;
    const int wr2 = wid >> 2, wc4 = wid & 3;
    const int wr4 = wid >> 1, wc1 = wid & 1;
    const float scale = 0.08838834764831845f;

#pragma unroll
    for (int i = 0; i < 8; i++) {
        int idx = tid + i * 256;
        int m = idx >> 5, d4 = (idx & 31) << 2;
        int r = m >> 4, s = m & 15;
        int hcol = (g * 4 + r) * HD + d4;
        float4 q = *(const float4*)(g_qkv + (size_t)(b * 16 + s) * QKV_N + hcol);
        float4 bb = *(const float4*)(bq + hcol);
        float4 o;
        o.x = tf32r((q.x + bb.x) * scale); o.y = tf32r((q.y + bb.y) * scale);
        o.z = tf32r((q.z + bb.z) * scale); o.w = tf32r((q.w + bb.w) * scale);
        *(float4*)(Qs + m * 132 + d4) = o;
    }
    if (tid < 64) rowsum[tid] = 0.f;
    __syncthreads();

    FragC acc_o[4];
#pragma unroll
    for (int j = 0; j < 4; j++) wmma::fill_fragment(acc_o[j], 0.0f);

    const int row = tid & 63, qq = tid >> 6;

    for (int t = 0; t < KVSPLIT / LT; t++) {
        const int l0 = split * KVSPLIT + t * LT;

        // K tile 64 x 128
#pragma unroll
        for (int i = 0; i < 8; i++) {
            int idx = tid + i * 256;
            int l = idx >> 5, d4 = (idx & 31) << 2;
            int lg = l0 + l;
            float4 kv;
            if (lg >= STARTP) {
                kv = *(const float4*)(g_qkv + (size_t)(b * 16 + (lg - STARTP)) * QKV_N
                                      + 4096 + g * HD + d4);
                float4 bb = *(const float4*)(bk + g * HD + d4);
                kv.x += bb.x; kv.y += bb.y; kv.z += bb.z; kv.w += bb.w;
            } else {
                kv = *(const float4*)(k_cache + (((size_t)b * MAXSEQ + lg) * NKV + g) * HD + d4);
            }
            kv.x = tf32r(kv.x); kv.y = tf32r(kv.y); kv.z = tf32r(kv.z); kv.w = tf32r(kv.w);
            *(float4*)(KVs + l * 136 + d4) = kv;
        }
        __syncthreads();

        // S = Q @ K^T
        FragC acc_s[2];
        wmma::fill_fragment(acc_s[0], 0.0f);
        wmma::fill_fragment(acc_s[1], 0.0f);
#pragma unroll
        for (int kk = 0; kk < HD; kk += 8) {
            FragA a[2]; FragBT bfr;
#pragma unroll
            for (int i = 0; i < 2; i++)
                wmma::load_matrix_sync(a[i], Qs + (wr2 * 32 + i * 16) * 132 + kk, 132);
            wmma::load_matrix_sync(bfr, KVs + (wc4 * 16) * 136 + kk, 136);
#pragma unroll
            for (int i = 0; i < 2; i++)
                wmma::mma_sync(acc_s[i], a[i], bfr, acc_s[i]);
        }
#pragma unroll
        for (int i = 0; i < 2; i++)
            wmma::store_matrix_sync(Ss + (wr2 * 32 + i * 16) * 72 + wc4 * 16,
                                    acc_s[i], 72, wmma::mem_row_major);
        __syncthreads();

        // exp (tf32-rounded) + partial row sums; V tile load
        {
            float part = 0.f;
            float* sp = Ss + row * 72 + qq * 16;
#pragma unroll
            for (int j = 0; j < 16; j++) {
                float e = tf32r(__expf(sp[j]));
                sp[j] = e;
                part += e;
            }
            tmp[qq * 64 + row] = part;
        }
#pragma unroll
        for (int i = 0; i < 8; i++) {
            int idx = tid + i * 256;
            int l = idx >> 5, d4 = (idx & 31) << 2;
            int lg = l0 + l;
            float4 v;
            if (lg >= STARTP) {
                v = *(const float4*)(g_qkv + (size_t)(b * 16 + (lg - STARTP)) * QKV_N
                                     + 5120 + g * HD + d4);
                float4 bb = *(const float4*)(bv + g * HD + d4);
                v.x += bb.x; v.y += bb.y; v.z += bb.z; v.w += bb.w;
            } else {
                v = *(const float4*)(v_cache + (((size_t)b * MAXSEQ + lg) * NKV + g) * HD + d4);
            }
            v.x = tf32r(v.x); v.y = tf32r(v.y); v.z = tf32r(v.z); v.w = tf32r(v.w);
            *(float4*)(KVs + l * 136 + d4) = v;
        }
        __syncthreads();

        if (tid < 64)
            rowsum[tid] += tmp[tid] + tmp[64 + tid] + tmp[128 + tid] + tmp[192 + tid];

        // O += P @ V
#pragma unroll
        for (int kk = 0; kk < LT; kk += 8) {
            FragA a;
            wmma::load_matrix_sync(a, Ss + (wr4 * 16) * 72 + kk, 72);
#pragma unroll
            for (int j = 0; j < 4; j++) {
                FragB bfr;
                wmma::load_matrix_sync(bfr, KVs + kk * 136 + wc1 * 64 + j * 16, 136);
                wmma::mma_sync(acc_o[j], a, bfr, acc_o[j]);
            }
        }
        __syncthreads();
    }

#pragma unroll
    for (int j = 0; j < 4; j++)
        wmma::store_matrix_sync(
            g_pvp + ((size_t)(split * NBG + bg) * 64 + wr4 * 16) * HD + wc1 * 64 + j * 16,
            acc_o[j], HD, wmma::mem_row_major);
    if (tid < 64)
        g_rsum[(size_t)(split * NBG + bg) * 64 + tid] = rowsum[tid];
}

// ---------------- kernel 3: combine splits, normalize, remap ------------------
__global__ void flash_combine_kernel()
{
    int t = blockIdx.x * 256 + threadIdx.x;
    int rowg = t >> 5;
    int c4 = (t & 31) << 2;
    float4 s = make_float4(0.f, 0.f, 0.f, 0.f);
    float den = 0.f;
#pragma unroll
    for (int sp = 0; sp < NSPLIT; sp++) {
        float4 v = *(const float4*)(g_pvp + ((size_t)sp * NBG * 64 + rowg) * HD + c4);
        s.x += v.x; s.y += v.y; s.z += v.z; s.w += v.w;
        den += g_rsum[(size_t)sp * NBG * 64 + rowg];
    }
    float inv = 1.f / den;
    s.x *= inv; s.y *= inv; s.z *= inv; s.w *= inv;
    int bg = rowg >> 6, qr = rowg & 63;
    int b = bg >> 3, g = bg & 7, r = qr >> 4, sq = qr & 15;
    *(float4*)(g_att + (size_t)(b * 16 + sq) * DIM + (g * 4 + r) * HD + c4) = s;
}

// ---------------- kernel 4: O projection split-K -------------------------------
__global__ void __launch_bounds__(256) o_kernel(const float* __restrict__ Wo)
{
    const int n0 = blockIdx.x * 128;
    const int kb = blockIdx.y * 1024;
    const int m0 = blockIdx.z * 64;
    const float* Abase = g_att + (size_t)m0 * DIM + kb;
    const float* Bbase = Wo + (size_t)kb * DIM + n0;
    float* Cpart = g_op + ((size_t)blockIdx.y * TOK + m0) * DIM + n0;
    GEMM_BODY(Abase, DIM, Bbase, DIM, Cpart, DIM)
}

__global__ void o_reduce_kernel(float* __restrict__ out, const float* __restrict__ bo)
{
    int i4 = (blockIdx.x * 256 + threadIdx.x) * 4;
    int n = i4 & (DIM - 1);
    float4 s = *(const float4*)(bo + n);
#pragma unroll
    for (int sp = 0; sp < SPLITO; sp++) {
        float4 v = *(const float4*)(g_op + (size_t)sp * TOK * DIM + i4);
        s.x += v.x; s.y += v.y; s.z += v.z; s.w += v.w;
    }
    *(float4*)(out + i4) = s;
}

// ---------------- launch ---------------------------------------------------------
extern "C" void kernel_launch(void* const* d_in, const int* in_sizes, int n_in,
                              void* d_out, int out_size)
{
    const float* x  = (const float*)d_in[0];
    const float* kc = (const float*)d_in[1];
    const float* vc = (const float*)d_in[2];
    const float* Wq = (const float*)d_in[3];  const float* bq = (const float*)d_in[4];
    const float* Wk = (const float*)d_in[5];  const float* bk = (const float*)d_in[6];
    const float* Wv = (const float*)d_in[7];  const float* bv = (const float*)d_in[8];
    const float* Wo = (const float*)d_in[9];  const float* bo = (const float*)d_in[10];
    float* out = (float*)d_out;

    cudaFuncSetAttribute(flash_kernel,
                         cudaFuncAttributeMaxDynamicSharedMemorySize, SMEM_FLASH);

    qkv_kernel<<<dim3(48, SPLITQ, 2), 256>>>(x, Wq, Wk, Wv);
    qkv_reduce_kernel<<<TOK * QKV_N / 1024, 256>>>();
    flash_kernel<<<dim3(NSPLIT, NBG), 256, SMEM_FLASH>>>(kc, vc, bq, bk, bv);
    flash_combine_kernel<<<512, 256>>>();
    o_kernel<<<dim3(32, SPLITO, 2), 256>>>(Wo);
    o_reduce_kernel<<<512, 256>>>(out, bo);
}

// round 5
// speedup vs baseline: 1.6551x; 1.0236x over previous
#include <cuda_runtime.h>
#include <cuda_bf16.h>
#include <mma.h>
#include <math.h>

using namespace nvcuda;

#define BSZ     8
#define QL      16
#define TOK     128
#define DIM     4096
#define NKV     8
#define HD      128
#define MAXSEQ  4096
#define STARTP  4080
#define KVLEN   4096
#define QKV_N   6144
#define NBG     64
#define NSPLIT  8
#define KVSPLIT 512
#define LT      64
#define NT_FL   (KVSPLIT / LT)
#define SPLITQ  8
#define SPLITO  8

__device__ float g_qkv[TOK * QKV_N];
__device__ float g_qkvp[SPLITQ * TOK * QKV_N];
__device__ float g_op[SPLITO * TOK * DIM];
__device__ float g_pvp[NSPLIT * NBG * 64 * HD];
__device__ float g_rsum[NSPLIT * NBG * 64];
__device__ float g_att[TOK * DIM];

__device__ __forceinline__ float tf32r(float x) { return wmma::__float_to_tf32(x); }

typedef wmma::fragment<wmma::accumulator, 16, 16, 8, float> FragC;
typedef wmma::fragment<wmma::matrix_a, 16, 16, 8, wmma::precision::tf32, wmma::row_major> FragA;
typedef wmma::fragment<wmma::matrix_b, 16, 16, 8, wmma::precision::tf32, wmma::row_major> FragB;
typedef wmma::fragment<wmma::matrix_b, 16, 16, 8, wmma::precision::tf32, wmma::col_major> FragBT;

template<int LDA, int LDB>
__device__ __forceinline__ void mma32(
    const float* __restrict__ As, const float* __restrict__ Bs,
    FragC (&acc)[2][2], int wr, int wc)
{
#pragma unroll
    for (int kk = 0; kk < 32; kk += 8) {
        FragA a[2]; FragB b[2];
#pragma unroll
        for (int i = 0; i < 2; i++)
            wmma::load_matrix_sync(a[i], As + (wr * 32 + i * 16) * LDA + kk, LDA);
#pragma unroll
        for (int j = 0; j < 2; j++)
            wmma::load_matrix_sync(b[j], Bs + kk * LDB + wc * 32 + j * 16, LDB);
#pragma unroll
        for (int i = 0; i < 2; i++)
#pragma unroll
            for (int j = 0; j < 2; j++)
                wmma::mma_sync(acc[i][j], a[i], b[j], acc[i][j]);
    }
}

// ---------------- split-K 64x128 GEMM body, NCHUNK chunks of k=32 -------------
#define GEMM_BODY(Abase, LDAG, Bbase, LDBG, CPART, LDC, NCHUNK)                    \
    __shared__ float As[2][64 * 36];                                               \
    __shared__ float Bs[2][32 * 132];                                              \
    const int tid = threadIdx.x;                                                   \
    const int wid = tid >> 5, wr = wid >> 2, wc = wid & 3;                         \
    int amr[2], akc[2], bkr[4], bnc[4];                                            \
    _Pragma("unroll")                                                              \
    for (int i = 0; i < 2; i++) { int idx = tid + i * 256; amr[i] = idx >> 3; akc[i] = (idx & 7) << 2; } \
    _Pragma("unroll")                                                              \
    for (int i = 0; i < 4; i++) { int idx = tid + i * 256; bkr[i] = idx >> 5; bnc[i] = (idx & 31) << 2; } \
    FragC acc[2][2];                                                               \
    _Pragma("unroll")                                                              \
    for (int i = 0; i < 2; i++)                                                    \
        _Pragma("unroll")                                                          \
        for (int j = 0; j < 2; j++) wmma::fill_fragment(acc[i][j], 0.0f);          \
    float4 ra[2], rb[4];                                                           \
    _Pragma("unroll")                                                              \
    for (int i = 0; i < 2; i++)                                                    \
        ra[i] = *(const float4*)((Abase) + (size_t)amr[i] * (LDAG) + akc[i]);      \
    _Pragma("unroll")                                                              \
    for (int i = 0; i < 4; i++)                                                    \
        rb[i] = *(const float4*)((Bbase) + (size_t)bkr[i] * (LDBG) + bnc[i]);      \
    _Pragma("unroll")                                                              \
    for (int i = 0; i < 2; i++) {                                                  \
        float4 c = ra[i];                                                          \
        c.x = tf32r(c.x); c.y = tf32r(c.y); c.z = tf32r(c.z); c.w = tf32r(c.w);    \
        *(float4*)(&As[0][amr[i] * 36 + akc[i]]) = c;                              \
    }                                                                              \
    _Pragma("unroll")                                                              \
    for (int i = 0; i < 4; i++) {                                                  \
        float4 c = rb[i];                                                          \
        c.x = tf32r(c.x); c.y = tf32r(c.y); c.z = tf32r(c.z); c.w = tf32r(c.w);    \
        *(float4*)(&Bs[0][bkr[i] * 132 + bnc[i]]) = c;                             \
    }                                                                              \
    __syncthreads();                                                               \
    for (int t = 0; t < (NCHUNK); t++) {                                           \
        int cur = t & 1;                                                           \
        if (t + 1 < (NCHUNK)) {                                                    \
            _Pragma("unroll")                                                      \
            for (int i = 0; i < 2; i++)                                            \
                ra[i] = *(const float4*)((Abase) + (size_t)amr[i] * (LDAG) + (t + 1) * 32 + akc[i]); \
            _Pragma("unroll")                                                      \
            for (int i = 0; i < 4; i++)                                            \
                rb[i] = *(const float4*)((Bbase) + (size_t)((t + 1) * 32 + bkr[i]) * (LDBG) + bnc[i]); \
        }                                                                          \
        mma32<36, 132>(As[cur], Bs[cur], acc, wr, wc);                             \
        if (t + 1 < (NCHUNK)) {                                                    \
            _Pragma("unroll")                                                      \
            for (int i = 0; i < 2; i++) {                                          \
                float4 c = ra[i];                                                  \
                c.x = tf32r(c.x); c.y = tf32r(c.y); c.z = tf32r(c.z); c.w = tf32r(c.w); \
                *(float4*)(&As[1 - cur][amr[i] * 36 + akc[i]]) = c;                \
            }                                                                      \
            _Pragma("unroll")                                                      \
            for (int i = 0; i < 4; i++) {                                          \
                float4 c = rb[i];                                                  \
                c.x = tf32r(c.x); c.y = tf32r(c.y); c.z = tf32r(c.z); c.w = tf32r(c.w); \
                *(float4*)(&Bs[1 - cur][bkr[i] * 132 + bnc[i]]) = c;               \
            }                                                                      \
        }                                                                          \
        __syncthreads();                                                           \
    }                                                                              \
    _Pragma("unroll")                                                              \
    for (int i = 0; i < 2; i++)                                                    \
        _Pragma("unroll")                                                          \
        for (int j = 0; j < 2; j++)                                                \
            wmma::store_matrix_sync((CPART) + (size_t)(wr * 32 + i * 16) * (LDC) + wc * 32 + j * 16, \
                                    acc[i][j], (LDC), wmma::mem_row_major);

// ---------------- kernel 1: QKV GEMM split-K(8) -------------------------------
__global__ void __launch_bounds__(256) qkv_kernel(
    const float* __restrict__ x,
    const float* __restrict__ Wq, const float* __restrict__ Wk,
    const float* __restrict__ Wv)
{
    const int n0 = blockIdx.x * 128;
    const int kb = blockIdx.y * (DIM / SPLITQ);
    const int m0 = blockIdx.z * 64;
    const float* B; int ldb, col;
    if (n0 < 4096)      { B = Wq; ldb = 4096; col = n0; }
    else if (n0 < 5120) { B = Wk; ldb = 1024; col = n0 - 4096; }
    else                { B = Wv; ldb = 1024; col = n0 - 5120; }

    const float* Abase = x + (size_t)m0 * DIM + kb;
    const float* Bbase = B + (size_t)kb * ldb + col;
    float* Cpart = g_qkvp + ((size_t)blockIdx.y * TOK + m0) * QKV_N + n0;
    GEMM_BODY(Abase, DIM, Bbase, ldb, Cpart, QKV_N, DIM / SPLITQ / 32)
}

__global__ void qkv_reduce_kernel()
{
    int i4 = (blockIdx.x * 256 + threadIdx.x) * 4;
    float4 s = make_float4(0.f, 0.f, 0.f, 0.f);
#pragma unroll
    for (int sp = 0; sp < SPLITQ; sp++) {
        float4 v = *(const float4*)(g_qkvp + (size_t)sp * TOK * QKV_N + i4);
        s.x += v.x; s.y += v.y; s.z += v.z; s.w += v.w;
    }
    *(float4*)(g_qkv + i4) = s;
}

// ---------------- kernel 2: flash attention, software-pipelined ---------------
#define SMEM_FLASH ((64*132 + 64*136 + 64*72 + 64 + 256) * 4)

__global__ void __launch_bounds__(256) flash_kernel(
    const float* __restrict__ k_cache, const float* __restrict__ v_cache,
    const float* __restrict__ bq, const float* __restrict__ bk,
    const float* __restrict__ bv)
{
    extern __shared__ float sm[];
    float* Qs     = sm;                  // [64][132]
    float* KVs    = Qs + 64 * 132;       // [64][136]
    float* Ss     = KVs + 64 * 136;      // [64][72]
    float* rowsum = Ss + 64 * 72;        // [64]
    float* tmp    = rowsum + 64;         // [4][64]

    const int split = blockIdx.x;
    const int bg = blockIdx.y, b = bg >> 3, g = bg & 7;
    const int tid = threadIdx.x, wid = tid >> 5;
    const int wr2 = wid >> 2, wc4 = wid & 3;
    const int wr4 = wid >> 1, wc1 = wid & 1;
    const float scale = 0.08838834764831845f;

    // per-thread fixed (l, d4) slots for KV tiles
    int lrow[8], dcol[8];
#pragma unroll
    for (int i = 0; i < 8; i++) {
        int idx = tid + i * 256;
        lrow[i] = idx >> 5; dcol[i] = (idx & 31) << 2;
    }

    // Q staging (bias + scale + round)
#pragma unroll
    for (int i = 0; i < 8; i++) {
        int m = lrow[i], d4 = dcol[i];
        int r = m >> 4, s = m & 15;
        int hcol = (g * 4 + r) * HD + d4;
        float4 q = *(const float4*)(g_qkv + (size_t)(b * 16 + s) * QKV_N + hcol);
        float4 bb = *(const float4*)(bq + hcol);
        float4 o;
        o.x = tf32r((q.x + bb.x) * scale); o.y = tf32r((q.y + bb.y) * scale);
        o.z = tf32r((q.z + bb.z) * scale); o.w = tf32r((q.w + bb.w) * scale);
        *(float4*)(Qs + m * 132 + d4) = o;
    }
    if (tid < 64) rowsum[tid] = 0.f;

    FragC acc_o[4];
#pragma unroll
    for (int j = 0; j < 4; j++) wmma::fill_fragment(acc_o[j], 0.0f);

    const int row = tid & 63, qq = tid >> 6;
    float4 rk[8], rv[8];

    // raw loads (no bias/round yet)
#define LOAD_KV(regs, l0, qoff, cache)                                             \
    _Pragma("unroll")                                                              \
    for (int i = 0; i < 8; i++) {                                                  \
        int lg = (l0) + lrow[i];                                                   \
        regs[i] = (lg >= STARTP)                                                   \
            ? *(const float4*)(g_qkv + (size_t)(b * 16 + (lg - STARTP)) * QKV_N + (qoff) + g * HD + dcol[i]) \
            : *(const float4*)((cache) + (((size_t)b * MAXSEQ + lg) * NKV + g) * HD + dcol[i]); \
    }

    // bias (new tokens only) + round + write to KVs
#define WRITE_KV(regs, l0, bias)                                                   \
    _Pragma("unroll")                                                              \
    for (int i = 0; i < 8; i++) {                                                  \
        float4 c = regs[i];                                                        \
        if ((l0) + lrow[i] >= STARTP) {                                            \
            float4 bb = *(const float4*)((bias) + g * HD + dcol[i]);               \
            c.x += bb.x; c.y += bb.y; c.z += bb.z; c.w += bb.w;                    \
        }                                                                          \
        c.x = tf32r(c.x); c.y = tf32r(c.y); c.z = tf32r(c.z); c.w = tf32r(c.w);    \
        *(float4*)(KVs + lrow[i] * 136 + dcol[i]) = c;                             \
    }

    const int lbase0 = split * KVSPLIT;
    LOAD_KV(rk, lbase0, 4096, k_cache)      // prologue: K[0] in flight

    for (int t = 0; t < NT_FL; t++) {
        const int l0 = lbase0 + t * LT;

        WRITE_KV(rk, l0, bk)                 // K[t] regs -> smem
        __syncthreads();

        // S = Q @ K^T  (overlapped with nothing to load: V issued after)
        FragC acc_s[2];
        wmma::fill_fragment(acc_s[0], 0.0f);
        wmma::fill_fragment(acc_s[1], 0.0f);
#pragma unroll
        for (int kk = 0; kk < HD; kk += 8) {
            FragA a[2]; FragBT bfr;
#pragma unroll
            for (int i = 0; i < 2; i++)
                wmma::load_matrix_sync(a[i], Qs + (wr2 * 32 + i * 16) * 132 + kk, 132);
            wmma::load_matrix_sync(bfr, KVs + (wc4 * 16) * 136 + kk, 136);
#pragma unroll
            for (int i = 0; i < 2; i++)
                wmma::mma_sync(acc_s[i], a[i], bfr, acc_s[i]);
        }
#pragma unroll
        for (int i = 0; i < 2; i++)
            wmma::store_matrix_sync(Ss + (wr2 * 32 + i * 16) * 72 + wc4 * 16,
                                    acc_s[i], 72, wmma::mem_row_major);
        __syncthreads();

        LOAD_KV(rv, l0, 5120, v_cache)       // V[t] in flight during exp
        {
            float part = 0.f;
            float* sp = Ss + row * 72 + qq * 16;
#pragma unroll
            for (int j = 0; j < 16; j++) {
                float e = tf32r(__expf(sp[j]));
                sp[j] = e;
                part += e;
            }
            tmp[qq * 64 + row] = part;
        }
        WRITE_KV(rv, l0, bv)                 // V[t] regs -> smem
        __syncthreads();

        if (tid < 64)
            rowsum[tid] += tmp[tid] + tmp[64 + tid] + tmp[128 + tid] + tmp[192 + tid];

        if (t + 1 < NT_FL) {
            LOAD_KV(rk, l0 + LT, 4096, k_cache)   // K[t+1] in flight during PV
        }

        // O += P @ V
#pragma unroll
        for (int kk = 0; kk < LT; kk += 8) {
            FragA a;
            wmma::load_matrix_sync(a, Ss + (wr4 * 16) * 72 + kk, 72);
#pragma unroll
            for (int j = 0; j < 4; j++) {
                FragB bfr;
                wmma::load_matrix_sync(bfr, KVs + kk * 136 + wc1 * 64 + j * 16, 136);
                wmma::mma_sync(acc_o[j], a, bfr, acc_o[j]);
            }
        }
        __syncthreads();
    }

#pragma unroll
    for (int j = 0; j < 4; j++)
        wmma::store_matrix_sync(
            g_pvp + ((size_t)(split * NBG + bg) * 64 + wr4 * 16) * HD + wc1 * 64 + j * 16,
            acc_o[j], HD, wmma::mem_row_major);
    if (tid < 64)
        g_rsum[(size_t)(split * NBG + bg) * 64 + tid] = rowsum[tid];
}

// ---------------- kernel 3: combine splits, normalize, remap ------------------
__global__ void flash_combine_kernel()
{
    int t = blockIdx.x * 256 + threadIdx.x;
    int rowg = t >> 5;
    int c4 = (t & 31) << 2;
    float4 s = make_float4(0.f, 0.f, 0.f, 0.f);
    float den = 0.f;
#pragma unroll
    for (int sp = 0; sp < NSPLIT; sp++) {
        float4 v = *(const float4*)(g_pvp + ((size_t)sp * NBG * 64 + rowg) * HD + c4);
        s.x += v.x; s.y += v.y; s.z += v.z; s.w += v.w;
        den += g_rsum[(size_t)sp * NBG * 64 + rowg];
    }
    float inv = 1.f / den;
    s.x *= inv; s.y *= inv; s.z *= inv; s.w *= inv;
    int bg = rowg >> 6, qr = rowg & 63;
    int b = bg >> 3, g = bg & 7, r = qr >> 4, sq = qr & 15;
    *(float4*)(g_att + (size_t)(b * 16 + sq) * DIM + (g * 4 + r) * HD + c4) = s;
}

// ---------------- kernel 4: O projection split-K(8) ----------------------------
__global__ void __launch_bounds__(256) o_kernel(const float* __restrict__ Wo)
{
    const int n0 = blockIdx.x * 128;
    const int kb = blockIdx.y * (DIM / SPLITO);
    const int m0 = blockIdx.z * 64;
    const float* Abase = g_att + (size_t)m0 * DIM + kb;
    const float* Bbase = Wo + (size_t)kb * DIM + n0;
    float* Cpart = g_op + ((size_t)blockIdx.y * TOK + m0) * DIM + n0;
    GEMM_BODY(Abase, DIM, Bbase, DIM, Cpart, DIM, DIM / SPLITO / 32)
}

__global__ void o_reduce_kernel(float* __restrict__ out, const float* __restrict__ bo)
{
    int i4 = (blockIdx.x * 256 + threadIdx.x) * 4;
    int n = i4 & (DIM - 1);
    float4 s = *(const float4*)(bo + n);
#pragma unroll
    for (int sp = 0; sp < SPLITO; sp++) {
        float4 v = *(const float4*)(g_op + (size_t)sp * TOK * DIM + i4);
        s.x += v.x; s.y += v.y; s.z += v.z; s.w += v.w;
    }
    *(float4*)(out + i4) = s;
}

// ---------------- launch ---------------------------------------------------------
extern "C" void kernel_launch(void* const* d_in, const int* in_sizes, int n_in,
                              void* d_out, int out_size)
{
    const float* x  = (const float*)d_in[0];
    const float* kc = (const float*)d_in[1];
    const float* vc = (const float*)d_in[2];
    const float* Wq = (const float*)d_in[3];  const float* bq = (const float*)d_in[4];
    const float* Wk = (const float*)d_in[5];  const float* bk = (const float*)d_in[6];
    const float* Wv = (const float*)d_in[7];  const float* bv = (const float*)d_in[8];
    const float* Wo = (const float*)d_in[9];  const float* bo = (const float*)d_in[10];
    float* out = (float*)d_out;

    cudaFuncSetAttribute(flash_kernel,
                         cudaFuncAttributeMaxDynamicSharedMemorySize, SMEM_FLASH);

    qkv_kernel<<<dim3(48, SPLITQ, 2), 256>>>(x, Wq, Wk, Wv);
    qkv_reduce_kernel<<<TOK * QKV_N / 1024, 256>>>();
    flash_kernel<<<dim3(NSPLIT, NBG), 256, SMEM_FLASH>>>(kc, vc, bq, bk, bv);
    flash_combine_kernel<<<512, 256>>>();
    o_kernel<<<dim3(32, SPLITO, 2), 256>>>(Wo);
    o_reduce_kernel<<<512, 256>>>(out, bo);
}

// round 6
// speedup vs baseline: 1.7220x; 1.0404x over previous
#include <cuda_runtime.h>
#include <cuda_bf16.h>
#include <mma.h>
#include <math.h>

using namespace nvcuda;

#define BSZ     8
#define QL      16
#define TOK     128
#define DIM     4096
#define NKV     8
#define HD      128
#define MAXSEQ  4096
#define STARTP  4080
#define KVLEN   4096
#define QKV_N   6144
#define NBG     64
#define NSPLIT  4
#define KVSPLIT 1024
#define LT      128
#define NT_FL   (KVSPLIT / LT)
#define SPLITQ  8
#define SPLITO  8

__device__ float g_qkv[TOK * QKV_N];
__device__ float g_qkvp[SPLITQ * TOK * QKV_N];
__device__ float g_op[SPLITO * TOK * DIM];
__device__ float g_pvp[NSPLIT * NBG * 64 * HD];
__device__ float g_rsum[NSPLIT * NBG * 64];
__device__ float g_att[TOK * DIM];

__device__ __forceinline__ float tf32r(float x) { return wmma::__float_to_tf32(x); }

typedef wmma::fragment<wmma::accumulator, 16, 16, 8, float> FragC;
typedef wmma::fragment<wmma::matrix_a, 16, 16, 8, wmma::precision::tf32, wmma::row_major> FragA;
typedef wmma::fragment<wmma::matrix_b, 16, 16, 8, wmma::precision::tf32, wmma::row_major> FragB;
typedef wmma::fragment<wmma::matrix_b, 16, 16, 8, wmma::precision::tf32, wmma::col_major> FragBT;

// ---------------- 128x128 split-K GEMM body, warp tile 32x64 -------------------
// Dynamic smem: As 2x[128*36], Bs 2x[32*132].
#define SMEM_GEMM ((2 * 128 * 36 + 2 * 32 * 132) * 4)

#define GEMM_BODY(Abase, LDAG, Bbase, LDBG, CPART, LDC, NCHUNK)                    \
    extern __shared__ float smg[];                                                 \
    float* As0 = smg;                                                              \
    float* As1 = smg + 128 * 36;                                                   \
    float* Bs0 = smg + 2 * 128 * 36;                                               \
    float* Bs1 = Bs0 + 32 * 132;                                                   \
    float* Asb[2] = {As0, As1};                                                    \
    float* Bsb[2] = {Bs0, Bs1};                                                    \
    const int tid = threadIdx.x;                                                   \
    const int wid = tid >> 5, wr = wid >> 1, wcx = wid & 1;                        \
    const int amr0 = tid >> 3, akc = (tid & 7) << 2;                               \
    const int bkr0 = tid >> 5, bnc = (tid & 31) << 2;                              \
    FragC acc[2][4];                                                               \
    _Pragma("unroll")                                                              \
    for (int i = 0; i < 2; i++)                                                    \
        _Pragma("unroll")                                                          \
        for (int j = 0; j < 4; j++) wmma::fill_fragment(acc[i][j], 0.0f);          \
    float4 ra[4], rb[4];                                                           \
    _Pragma("unroll")                                                              \
    for (int i = 0; i < 4; i++)                                                    \
        ra[i] = *(const float4*)((Abase) + (size_t)(amr0 + 32 * i) * (LDAG) + akc); \
    _Pragma("unroll")                                                              \
    for (int i = 0; i < 4; i++)                                                    \
        rb[i] = *(const float4*)((Bbase) + (size_t)(bkr0 + 8 * i) * (LDBG) + bnc); \
    _Pragma("unroll")                                                              \
    for (int i = 0; i < 4; i++) {                                                  \
        float4 c = ra[i];                                                          \
        c.x = tf32r(c.x); c.y = tf32r(c.y); c.z = tf32r(c.z); c.w = tf32r(c.w);    \
        *(float4*)(&As0[(amr0 + 32 * i) * 36 + akc]) = c;                          \
    }                                                                              \
    _Pragma("unroll")                                                              \
    for (int i = 0; i < 4; i++) {                                                  \
        float4 c = rb[i];                                                          \
        c.x = tf32r(c.x); c.y = tf32r(c.y); c.z = tf32r(c.z); c.w = tf32r(c.w);    \
        *(float4*)(&Bs0[(bkr0 + 8 * i) * 132 + bnc]) = c;                          \
    }                                                                              \
    __syncthreads();                                                               \
    for (int t = 0; t < (NCHUNK); t++) {                                           \
        int cur = t & 1;                                                           \
        if (t + 1 < (NCHUNK)) {                                                    \
            _Pragma("unroll")                                                      \
            for (int i = 0; i < 4; i++)                                            \
                ra[i] = *(const float4*)((Abase) + (size_t)(amr0 + 32 * i) * (LDAG) + (t + 1) * 32 + akc); \
            _Pragma("unroll")                                                      \
            for (int i = 0; i < 4; i++)                                            \
                rb[i] = *(const float4*)((Bbase) + (size_t)((t + 1) * 32 + bkr0 + 8 * i) * (LDBG) + bnc); \
        }                                                                          \
        _Pragma("unroll")                                                          \
        for (int kk = 0; kk < 32; kk += 8) {                                       \
            FragA a[2]; FragB b[4];                                                \
            _Pragma("unroll")                                                      \
            for (int i = 0; i < 2; i++)                                            \
                wmma::load_matrix_sync(a[i], Asb[cur] + (wr * 32 + i * 16) * 36 + kk, 36); \
            _Pragma("unroll")                                                      \
            for (int j = 0; j < 4; j++)                                            \
                wmma::load_matrix_sync(b[j], Bsb[cur] + kk * 132 + wcx * 64 + j * 16, 132); \
            _Pragma("unroll")                                                      \
            for (int i = 0; i < 2; i++)                                            \
                _Pragma("unroll")                                                  \
                for (int j = 0; j < 4; j++)                                        \
                    wmma::mma_sync(acc[i][j], a[i], b[j], acc[i][j]);              \
        }                                                                          \
        if (t + 1 < (NCHUNK)) {                                                    \
            _Pragma("unroll")                                                      \
            for (int i = 0; i < 4; i++) {                                          \
                float4 c = ra[i];                                                  \
                c.x = tf32r(c.x); c.y = tf32r(c.y); c.z = tf32r(c.z); c.w = tf32r(c.w); \
                *(float4*)(&Asb[1 - cur][(amr0 + 32 * i) * 36 + akc]) = c;         \
            }                                                                      \
            _Pragma("unroll")                                                      \
            for (int i = 0; i < 4; i++) {                                          \
                float4 c = rb[i];                                                  \
                c.x = tf32r(c.x); c.y = tf32r(c.y); c.z = tf32r(c.z); c.w = tf32r(c.w); \
                *(float4*)(&Bsb[1 - cur][(bkr0 + 8 * i) * 132 + bnc]) = c;         \
            }                                                                      \
        }                                                                          \
        __syncthreads();                                                           \
    }                                                                              \
    _Pragma("unroll")                                                              \
    for (int i = 0; i < 2; i++)                                                    \
        _Pragma("unroll")                                                          \
        for (int j = 0; j < 4; j++)                                                \
            wmma::store_matrix_sync((CPART) + (size_t)(wr * 32 + i * 16) * (LDC) + wcx * 64 + j * 16, \
                                    acc[i][j], (LDC), wmma::mem_row_major);

// ---------------- kernel 1: QKV GEMM split-K(8), M=128 -------------------------
__global__ void __launch_bounds__(256) qkv_kernel(
    const float* __restrict__ x,
    const float* __restrict__ Wq, const float* __restrict__ Wk,
    const float* __restrict__ Wv)
{
    const int n0 = blockIdx.x * 128;
    const int kb = blockIdx.y * (DIM / SPLITQ);
    const float* B; int ldb, col;
    if (n0 < 4096)      { B = Wq; ldb = 4096; col = n0; }
    else if (n0 < 5120) { B = Wk; ldb = 1024; col = n0 - 4096; }
    else                { B = Wv; ldb = 1024; col = n0 - 5120; }

    const float* Abase = x + kb;
    const float* Bbase = B + (size_t)kb * ldb + col;
    float* Cpart = g_qkvp + (size_t)blockIdx.y * TOK * QKV_N + n0;
    GEMM_BODY(Abase, DIM, Bbase, ldb, Cpart, QKV_N, DIM / SPLITQ / 32)
}

__global__ void qkv_reduce_kernel()
{
    int i4 = (blockIdx.x * 256 + threadIdx.x) * 4;
    float4 s = make_float4(0.f, 0.f, 0.f, 0.f);
#pragma unroll
    for (int sp = 0; sp < SPLITQ; sp++) {
        float4 v = *(const float4*)(g_qkvp + (size_t)sp * TOK * QKV_N + i4);
        s.x += v.x; s.y += v.y; s.z += v.z; s.w += v.w;
    }
    *(float4*)(g_qkv + i4) = s;
}

// ---------------- kernel 2: flash attention, LT=128 ----------------------------
// smem: Qs[64*132], KVs[128*136], Ss[64*136], rowsum[64], tmp[256]
#define SMEM_FLASH ((64 * 132 + 128 * 136 + 64 * 136 + 64 + 256) * 4)

__global__ void __launch_bounds__(256) flash_kernel(
    const float* __restrict__ k_cache, const float* __restrict__ v_cache,
    const float* __restrict__ bq, const float* __restrict__ bk,
    const float* __restrict__ bv)
{
    extern __shared__ float sm[];
    float* Qs     = sm;                      // [64][132]
    float* KVs    = Qs + 64 * 132;           // [128][136]
    float* Ss     = KVs + 128 * 136;         // [64][136]
    float* rowsum = Ss + 64 * 136;           // [64]
    float* tmp    = rowsum + 64;             // [4][64]

    const int split = blockIdx.x;
    const int bg = blockIdx.y, b = bg >> 3, g = bg & 7;
    const int tid = threadIdx.x, wid = tid >> 5;
    const int wr2 = wid >> 2, wc4 = wid & 3;   // S: 2x4 grid of 32x32
    const int wr4 = wid >> 1, wc1 = wid & 1;   // PV: 4x2 grid of 16x64
    const float scale = 0.08838834764831845f;

    const int lr0 = tid >> 5;                  // row base (stride 8)
    const int d4  = (tid & 31) << 2;           // fixed col

    // Q staging (bias + scale + round): 64 x 128
#pragma unroll
    for (int i = 0; i < 8; i++) {
        int m = lr0 + 8 * i;
        int r = m >> 4, s = m & 15;
        int hcol = (g * 4 + r) * HD + d4;
        float4 q = *(const float4*)(g_qkv + (size_t)(b * 16 + s) * QKV_N + hcol);
        float4 bb = *(const float4*)(bq + hcol);
        float4 o;
        o.x = tf32r((q.x + bb.x) * scale); o.y = tf32r((q.y + bb.y) * scale);
        o.z = tf32r((q.z + bb.z) * scale); o.w = tf32r((q.w + bb.w) * scale);
        *(float4*)(Qs + m * 132 + d4) = o;
    }
    if (tid < 64) rowsum[tid] = 0.f;

    FragC acc_o[4];
#pragma unroll
    for (int j = 0; j < 4; j++) wmma::fill_fragment(acc_o[j], 0.0f);

    const int row = tid & 63, qq = tid >> 6;
    float4 rk[16], rv[16];

#define LOAD_KV(regs, l0, qoff, cache)                                             \
    _Pragma("unroll")                                                              \
    for (int i = 0; i < 16; i++) {                                                 \
        int lg = (l0) + lr0 + 8 * i;                                               \
        regs[i] = (lg >= STARTP)                                                   \
            ? *(const float4*)(g_qkv + (size_t)(b * 16 + (lg - STARTP)) * QKV_N + (qoff) + g * HD + d4) \
            : *(const float4*)((cache) + (((size_t)b * MAXSEQ + lg) * NKV + g) * HD + d4); \
    }

#define WRITE_KV(regs, l0, bias)                                                   \
    _Pragma("unroll")                                                              \
    for (int i = 0; i < 16; i++) {                                                 \
        float4 c = regs[i];                                                        \
        if ((l0) + lr0 + 8 * i >= STARTP) {                                        \
            float4 bb = *(const float4*)((bias) + g * HD + d4);                    \
            c.x += bb.x; c.y += bb.y; c.z += bb.z; c.w += bb.w;                    \
        }                                                                          \
        c.x = tf32r(c.x); c.y = tf32r(c.y); c.z = tf32r(c.z); c.w = tf32r(c.w);    \
        *(float4*)(KVs + (lr0 + 8 * i) * 136 + d4) = c;                            \
    }

    const int lbase0 = split * KVSPLIT;
    LOAD_KV(rk, lbase0, 4096, k_cache)

    for (int t = 0; t < NT_FL; t++) {
        const int l0 = lbase0 + t * LT;

        WRITE_KV(rk, l0, bk)
        __syncthreads();

        // S = Q @ K^T : 64x128, k=HD=128; warp tile 32x32
        FragC acc_s[2][2];
#pragma unroll
        for (int i = 0; i < 2; i++)
#pragma unroll
            for (int j = 0; j < 2; j++) wmma::fill_fragment(acc_s[i][j], 0.0f);
#pragma unroll
        for (int kk = 0; kk < HD; kk += 8) {
            FragA a[2]; FragBT bt[2];
#pragma unroll
            for (int i = 0; i < 2; i++)
                wmma::load_matrix_sync(a[i], Qs + (wr2 * 32 + i * 16) * 132 + kk, 132);
#pragma unroll
            for (int j = 0; j < 2; j++)
                wmma::load_matrix_sync(bt[j], KVs + (wc4 * 32 + j * 16) * 136 + kk, 136);
#pragma unroll
            for (int i = 0; i < 2; i++)
#pragma unroll
                for (int j = 0; j < 2; j++)
                    wmma::mma_sync(acc_s[i][j], a[i], bt[j], acc_s[i][j]);
        }
#pragma unroll
        for (int i = 0; i < 2; i++)
#pragma unroll
            for (int j = 0; j < 2; j++)
                wmma::store_matrix_sync(Ss + (wr2 * 32 + i * 16) * 136 + wc4 * 32 + j * 16,
                                        acc_s[i][j], 136, wmma::mem_row_major);
        __syncthreads();

        LOAD_KV(rv, l0, 5120, v_cache)     // V in flight during exp
        {
            float part = 0.f;
            float* sp = Ss + row * 136 + qq * 32;
#pragma unroll
            for (int j = 0; j < 32; j++) {
                float e = tf32r(__expf(sp[j]));
                sp[j] = e;
                part += e;
            }
            tmp[qq * 64 + row] = part;
        }
        WRITE_KV(rv, l0, bv)
        __syncthreads();

        if (tid < 64)
            rowsum[tid] += tmp[tid] + tmp[64 + tid] + tmp[128 + tid] + tmp[192 + tid];

        if (t + 1 < NT_FL) {
            LOAD_KV(rk, l0 + LT, 4096, k_cache)   // K[t+1] in flight during PV
        }

        // O += P @ V : 64x128, k=LT=128; warp tile 16x64
#pragma unroll
        for (int kk = 0; kk < LT; kk += 8) {
            FragA a;
            wmma::load_matrix_sync(a, Ss + (wr4 * 16) * 136 + kk, 136);
#pragma unroll
            for (int j = 0; j < 4; j++) {
                FragB bfr;
                wmma::load_matrix_sync(bfr, KVs + kk * 136 + wc1 * 64 + j * 16, 136);
                wmma::mma_sync(acc_o[j], a, bfr, acc_o[j]);
            }
        }
        __syncthreads();
    }

#pragma unroll
    for (int j = 0; j < 4; j++)
        wmma::store_matrix_sync(
            g_pvp + ((size_t)(split * NBG + bg) * 64 + wr4 * 16) * HD + wc1 * 64 + j * 16,
            acc_o[j], HD, wmma::mem_row_major);
    if (tid < 64)
        g_rsum[(size_t)(split * NBG + bg) * 64 + tid] = rowsum[tid];
}

// ---------------- kernel 3: combine splits, normalize, remap -------------------
__global__ void flash_combine_kernel()
{
    int t = blockIdx.x * 256 + threadIdx.x;
    int rowg = t >> 5;
    int c4 = (t & 31) << 2;
    float4 s = make_float4(0.f, 0.f, 0.f, 0.f);
    float den = 0.f;
#pragma unroll
    for (int sp = 0; sp < NSPLIT; sp++) {
        float4 v = *(const float4*)(g_pvp + ((size_t)sp * NBG * 64 + rowg) * HD + c4);
        s.x += v.x; s.y += v.y; s.z += v.z; s.w += v.w;
        den += g_rsum[(size_t)sp * NBG * 64 + rowg];
    }
    float inv = 1.f / den;
    s.x *= inv; s.y *= inv; s.z *= inv; s.w *= inv;
    int bg = rowg >> 6, qr = rowg & 63;
    int b = bg >> 3, g = bg & 7, r = qr >> 4, sq = qr & 15;
    *(float4*)(g_att + (size_t)(b * 16 + sq) * DIM + (g * 4 + r) * HD + c4) = s;
}

// ---------------- kernel 4: O projection split-K(8), M=128 ---------------------
__global__ void __launch_bounds__(256) o_kernel(const float* __restrict__ Wo)
{
    const int n0 = blockIdx.x * 128;
    const int kb = blockIdx.y * (DIM / SPLITO);
    const float* Abase = g_att + kb;
    const float* Bbase = Wo + (size_t)kb * DIM + n0;
    float* Cpart = g_op + (size_t)blockIdx.y * TOK * DIM + n0;
    GEMM_BODY(Abase, DIM, Bbase, DIM, Cpart, DIM, DIM / SPLITO / 32)
}

__global__ void o_reduce_kernel(float* __restrict__ out, const float* __restrict__ bo)
{
    int i4 = (blockIdx.x * 256 + threadIdx.x) * 4;
    int n = i4 & (DIM - 1);
    float4 s = *(const float4*)(bo + n);
#pragma unroll
    for (int sp = 0; sp < SPLITO; sp++) {
        float4 v = *(const float4*)(g_op + (size_t)sp * TOK * DIM + i4);
        s.x += v.x; s.y += v.y; s.z += v.z; s.w += v.w;
    }
    *(float4*)(out + i4) = s;
}

// ---------------- launch ---------------------------------------------------------
extern "C" void kernel_launch(void* const* d_in, const int* in_sizes, int n_in,
                              void* d_out, int out_size)
{
    const float* x  = (const float*)d_in[0];
    const float* kc = (const float*)d_in[1];
    const float* vc = (const float*)d_in[2];
    const float* Wq = (const float*)d_in[3];  const float* bq = (const float*)d_in[4];
    const float* Wk = (const float*)d_in[5];  const float* bk = (const float*)d_in[6];
    const float* Wv = (const float*)d_in[7];  const float* bv = (const float*)d_in[8];
    const float* Wo = (const float*)d_in[9];  const float* bo = (const float*)d_in[10];
    float* out = (float*)d_out;

    cudaFuncSetAttribute(flash_kernel,
                         cudaFuncAttributeMaxDynamicSharedMemorySize, SMEM_FLASH);
    cudaFuncSetAttribute(qkv_kernel,
                         cudaFuncAttributeMaxDynamicSharedMemorySize, SMEM_GEMM);
    cudaFuncSetAttribute(o_kernel,
                         cudaFuncAttributeMaxDynamicSharedMemorySize, SMEM_GEMM);

    qkv_kernel<<<dim3(48, SPLITQ), 256, SMEM_GEMM>>>(x, Wq, Wk, Wv);
    qkv_reduce_kernel<<<TOK * QKV_N / 1024, 256>>>();
    flash_kernel<<<dim3(NSPLIT, NBG), 256, SMEM_FLASH>>>(kc, vc, bq, bk, bv);
    flash_combine_kernel<<<512, 256>>>();
    o_kernel<<<dim3(32, SPLITO), 256, SMEM_GEMM>>>(Wo);
    o_reduce_kernel<<<512, 256>>>(out, bo);
}

// round 8
// speedup vs baseline: 1.8572x; 1.0785x over previous
#include <cuda_runtime.h>
#include <cuda_bf16.h>
#include <mma.h>
#include <math.h>

using namespace nvcuda;

#define BSZ     8
#define QL      16
#define TOK     128
#define DIM     4096
#define NKV     8
#define HD      128
#define MAXSEQ  4096
#define STARTP  4080
#define KVLEN   4096
#define QKV_N   6144
#define NBG     64
#define NSPLIT  4
#define KVSPLIT 1024
#define LT      128
#define NT_FL   (KVSPLIT / LT)
#define SPLITQ  8
#define SPLITO  8
#define NTHR    512

__device__ float g_qkv[TOK * QKV_N];
__device__ float g_qkvp[SPLITQ * TOK * QKV_N];
__device__ float g_op[SPLITO * TOK * DIM];
__device__ float g_pvp[NSPLIT * NBG * 64 * HD];
__device__ float g_rsum[NSPLIT * NBG * 64];
__device__ float g_att[TOK * DIM];

__device__ __forceinline__ float tf32r(float x) { return wmma::__float_to_tf32(x); }

typedef wmma::fragment<wmma::accumulator, 16, 16, 8, float> FragC;
typedef wmma::fragment<wmma::matrix_a, 16, 16, 8, wmma::precision::tf32, wmma::row_major> FragA;
typedef wmma::fragment<wmma::matrix_b, 16, 16, 8, wmma::precision::tf32, wmma::row_major> FragB;
typedef wmma::fragment<wmma::matrix_b, 16, 16, 8, wmma::precision::tf32, wmma::col_major> FragBT;

// ---------------- 128x128 split-K GEMM body, 512 thr, warp tile 32x32 ----------
#define SMEM_GEMM ((2 * 128 * 36 + 2 * 32 * 132) * 4)

#define GEMM_BODY(Abase, LDAG, Bbase, LDBG, CPART, LDC, NCHUNK)                    \
    extern __shared__ float smg[];                                                 \
    float* Asb[2] = {smg, smg + 128 * 36};                                         \
    float* Bsb[2] = {smg + 2 * 128 * 36, smg + 2 * 128 * 36 + 32 * 132};           \
    const int tid = threadIdx.x;                                                   \
    const int wid = tid >> 5, wr = wid >> 2, wcx = wid & 3;                        \
    const int amr0 = tid >> 3, akc = (tid & 7) << 2;                               \
    const int bkr0 = tid >> 5, bnc = (tid & 31) << 2;                              \
    FragC acc[2][2];                                                               \
    _Pragma("unroll")                                                              \
    for (int i = 0; i < 2; i++)                                                    \
        _Pragma("unroll")                                                          \
        for (int j = 0; j < 2; j++) wmma::fill_fragment(acc[i][j], 0.0f);          \
    float4 ra[2], rb[2];                                                           \
    _Pragma("unroll")                                                              \
    for (int i = 0; i < 2; i++)                                                    \
        ra[i] = *(const float4*)((Abase) + (size_t)(amr0 + 64 * i) * (LDAG) + akc); \
    _Pragma("unroll")                                                              \
    for (int i = 0; i < 2; i++)                                                    \
        rb[i] = *(const float4*)((Bbase) + (size_t)(bkr0 + 16 * i) * (LDBG) + bnc); \
    _Pragma("unroll")                                                              \
    for (int i = 0; i < 2; i++) {                                                  \
        float4 c = ra[i];                                                          \
        c.x = tf32r(c.x); c.y = tf32r(c.y); c.z = tf32r(c.z); c.w = tf32r(c.w);    \
        *(float4*)(&Asb[0][(amr0 + 64 * i) * 36 + akc]) = c;                       \
    }                                                                              \
    _Pragma("unroll")                                                              \
    for (int i = 0; i < 2; i++) {                                                  \
        float4 c = rb[i];                                                          \
        c.x = tf32r(c.x); c.y = tf32r(c.y); c.z = tf32r(c.z); c.w = tf32r(c.w);    \
        *(float4*)(&Bsb[0][(bkr0 + 16 * i) * 132 + bnc]) = c;                      \
    }                                                                              \
    __syncthreads();                                                               \
    for (int t = 0; t < (NCHUNK); t++) {                                           \
        int cur = t & 1;                                                           \
        if (t + 1 < (NCHUNK)) {                                                    \
            _Pragma("unroll")                                                      \
            for (int i = 0; i < 2; i++)                                            \
                ra[i] = *(const float4*)((Abase) + (size_t)(amr0 + 64 * i) * (LDAG) + (t + 1) * 32 + akc); \
            _Pragma("unroll")                                                      \
            for (int i = 0; i < 2; i++)                                            \
                rb[i] = *(const float4*)((Bbase) + (size_t)((t + 1) * 32 + bkr0 + 16 * i) * (LDBG) + bnc); \
        }                                                                          \
        _Pragma("unroll")                                                          \
        for (int kk = 0; kk < 32; kk += 8) {                                       \
            FragA a[2]; FragB b[2];                                                \
            _Pragma("unroll")                                                      \
            for (int i = 0; i < 2; i++)                                            \
                wmma::load_matrix_sync(a[i], Asb[cur] + (wr * 32 + i * 16) * 36 + kk, 36); \
            _Pragma("unroll")                                                      \
            for (int j = 0; j < 2; j++)                                            \
                wmma::load_matrix_sync(b[j], Bsb[cur] + kk * 132 + wcx * 32 + j * 16, 132); \
            _Pragma("unroll")                                                      \
            for (int i = 0; i < 2; i++)                                            \
                _Pragma("unroll")                                                  \
                for (int j = 0; j < 2; j++)                                        \
                    wmma::mma_sync(acc[i][j], a[i], b[j], acc[i][j]);              \
        }                                                                          \
        if (t + 1 < (NCHUNK)) {                                                    \
            _Pragma("unroll")                                                      \
            for (int i = 0; i < 2; i++) {                                          \
                float4 c = ra[i];                                                  \
                c.x = tf32r(c.x); c.y = tf32r(c.y); c.z = tf32r(c.z); c.w = tf32r(c.w); \
                *(float4*)(&Asb[1 - cur][(amr0 + 64 * i) * 36 + akc]) = c;         \
            }                                                                      \
            _Pragma("unroll")                                                      \
            for (int i = 0; i < 2; i++) {                                          \
                float4 c = rb[i];                                                  \
                c.x = tf32r(c.x); c.y = tf32r(c.y); c.z = tf32r(c.z); c.w = tf32r(c.w); \
                *(float4*)(&Bsb[1 - cur][(bkr0 + 16 * i) * 132 + bnc]) = c;        \
            }                                                                      \
        }                                                                          \
        __syncthreads();                                                           \
    }                                                                              \
    _Pragma("unroll")                                                              \
    for (int i = 0; i < 2; i++)                                                    \
        _Pragma("unroll")                                                          \
        for (int j = 0; j < 2; j++)                                                \
            wmma::store_matrix_sync((CPART) + (size_t)(wr * 32 + i * 16) * (LDC) + wcx * 32 + j * 16, \
                                    acc[i][j], (LDC), wmma::mem_row_major);

// ---------------- kernel 1: QKV GEMM split-K(8), 512 thr -----------------------
__global__ void __launch_bounds__(NTHR) qkv_kernel(
    const float* __restrict__ x,
    const float* __restrict__ Wq, const float* __restrict__ Wk,
    const float* __restrict__ Wv)
{
    const int n0 = blockIdx.x * 128;
    const int kb = blockIdx.y * (DIM / SPLITQ);
    const float* B; int ldb, col;
    if (n0 < 4096)      { B = Wq; ldb = 4096; col = n0; }
    else if (n0 < 5120) { B = Wk; ldb = 1024; col = n0 - 4096; }
    else                { B = Wv; ldb = 1024; col = n0 - 5120; }

    const float* Abase = x + kb;
    const float* Bbase = B + (size_t)kb * ldb + col;
    float* Cpart = g_qkvp + (size_t)blockIdx.y * TOK * QKV_N + n0;
    GEMM_BODY(Abase, DIM, Bbase, ldb, Cpart, QKV_N, DIM / SPLITQ / 32)
}

__global__ void qkv_reduce_kernel()
{
    int i4 = (blockIdx.x * 256 + threadIdx.x) * 4;
    float4 s = make_float4(0.f, 0.f, 0.f, 0.f);
#pragma unroll
    for (int sp = 0; sp < SPLITQ; sp++) {
        float4 v = *(const float4*)(g_qkvp + (size_t)sp * TOK * QKV_N + i4);
        s.x += v.x; s.y += v.y; s.z += v.z; s.w += v.w;
    }
    *(float4*)(g_qkv + i4) = s;
}

// ---------------- kernel 2: flash attention, 512 thr, LT=128 -------------------
// smem: Qs[64*132], KVs[128*136], Ss[64*136], rowsum[64], tmp[512]
#define SMEM_FLASH ((64 * 132 + 128 * 136 + 64 * 136 + 64 + 512) * 4)

__global__ void __launch_bounds__(NTHR) flash_kernel(
    const float* __restrict__ k_cache, const float* __restrict__ v_cache,
    const float* __restrict__ bq, const float* __restrict__ bk,
    const float* __restrict__ bv)
{
    extern __shared__ float sm[];
    float* Qs     = sm;                      // [64][132]
    float* KVs    = Qs + 64 * 132;           // [128][136]
    float* Ss     = KVs + 128 * 136;         // [64][136]
    float* rowsum = Ss + 64 * 136;           // [64]
    float* tmp    = rowsum + 64;             // [8][64]

    const int split = blockIdx.x;
    const int bg = blockIdx.y, b = bg >> 3, g = bg & 7;
    const int tid = threadIdx.x, wid = tid >> 5;
    const int wr4 = wid >> 2, wc4 = wid & 3;   // 4x4 warp grid
    const float scale = 0.08838834764831845f;

    const int lr0 = tid >> 5;                  // 0..15, row stride 16
    const int d4  = (tid & 31) << 2;

    // Q staging: 64 x 128 (2048 f4 / 512 thr = 4)
#pragma unroll
    for (int i = 0; i < 4; i++) {
        int m = lr0 + 16 * i;
        int r = m >> 4, s = m & 15;
        int hcol = (g * 4 + r) * HD + d4;
        float4 q = *(const float4*)(g_qkv + (size_t)(b * 16 + s) * QKV_N + hcol);
        float4 bb = *(const float4*)(bq + hcol);
        float4 o;
        o.x = tf32r((q.x + bb.x) * scale); o.y = tf32r((q.y + bb.y) * scale);
        o.z = tf32r((q.z + bb.z) * scale); o.w = tf32r((q.w + bb.w) * scale);
        *(float4*)(Qs + m * 132 + d4) = o;
    }
    if (tid < 64) rowsum[tid] = 0.f;

    FragC acc_o[2];
#pragma unroll
    for (int j = 0; j < 2; j++) wmma::fill_fragment(acc_o[j], 0.0f);

    const int row = tid & 63, qq = tid >> 6;   // 8 col-chunks of 16
    float4 rk[8], rv[8];

#define LOAD_KV(regs, l0, qoff, cache)                                             \
    _Pragma("unroll")                                                              \
    for (int i = 0; i < 8; i++) {                                                  \
        int lg = (l0) + lr0 + 16 * i;                                              \
        regs[i] = (lg >= STARTP)                                                   \
            ? *(const float4*)(g_qkv + (size_t)(b * 16 + (lg - STARTP)) * QKV_N + (qoff) + g * HD + d4) \
            : *(const float4*)((cache) + (((size_t)b * MAXSEQ + lg) * NKV + g) * HD + d4); \
    }

#define WRITE_KV(regs, l0, bias)                                                   \
    _Pragma("unroll")                                                              \
    for (int i = 0; i < 8; i++) {                                                  \
        float4 c = regs[i];                                                        \
        if ((l0) + lr0 + 16 * i >= STARTP) {                                       \
            float4 bb = *(const float4*)((bias) + g * HD + d4);                    \
            c.x += bb.x; c.y += bb.y; c.z += bb.z; c.w += bb.w;                    \
        }                                                                          \
        c.x = tf32r(c.x); c.y = tf32r(c.y); c.z = tf32r(c.z); c.w = tf32r(c.w);    \
        *(float4*)(KVs + (lr0 + 16 * i) * 136 + d4) = c;                           \
    }

    const int lbase0 = split * KVSPLIT;
    LOAD_KV(rk, lbase0, 4096, k_cache)

    for (int t = 0; t < NT_FL; t++) {
        const int l0 = lbase0 + t * LT;

        WRITE_KV(rk, l0, bk)
        __syncthreads();

        // S = Q @ K^T : 64x128, k=128; warp tile 16x32
        FragC acc_s[2];
        wmma::fill_fragment(acc_s[0], 0.0f);
        wmma::fill_fragment(acc_s[1], 0.0f);
#pragma unroll
        for (int kk = 0; kk < HD; kk += 8) {
            FragA a; FragBT bt[2];
            wmma::load_matrix_sync(a, Qs + (wr4 * 16) * 132 + kk, 132);
#pragma unroll
            for (int j = 0; j < 2; j++)
                wmma::load_matrix_sync(bt[j], KVs + (wc4 * 32 + j * 16) * 136 + kk, 136);
#pragma unroll
            for (int j = 0; j < 2; j++)
                wmma::mma_sync(acc_s[j], a, bt[j], acc_s[j]);
        }
#pragma unroll
        for (int j = 0; j < 2; j++)
            wmma::store_matrix_sync(Ss + (wr4 * 16) * 136 + wc4 * 32 + j * 16,
                                    acc_s[j], 136, wmma::mem_row_major);
        __syncthreads();

        LOAD_KV(rv, l0, 5120, v_cache)     // V in flight during exp
        {
            float part = 0.f;
            float* sp = Ss + row * 136 + qq * 16;
#pragma unroll
            for (int j = 0; j < 16; j++) {
                float e = tf32r(__expf(sp[j]));
                sp[j] = e;
                part += e;
            }
            tmp[qq * 64 + row] = part;
        }
        WRITE_KV(rv, l0, bv)
        __syncthreads();

        if (tid < 64) {
            float s = 0.f;
#pragma unroll
            for (int q8 = 0; q8 < 8; q8++) s += tmp[q8 * 64 + tid];
            rowsum[tid] += s;
        }

        if (t + 1 < NT_FL) {
            LOAD_KV(rk, l0 + LT, 4096, k_cache)
        }

        // O += P @ V : 64x128, k=128; warp tile 16x32
#pragma unroll
        for (int kk = 0; kk < LT; kk += 8) {
            FragA a;
            wmma::load_matrix_sync(a, Ss + (wr4 * 16) * 136 + kk, 136);
#pragma unroll
            for (int j = 0; j < 2; j++) {
                FragB bfr;
                wmma::load_matrix_sync(bfr, KVs + kk * 136 + wc4 * 32 + j * 16, 136);
                wmma::mma_sync(acc_o[j], a, bfr, acc_o[j]);
            }
        }
        __syncthreads();
    }

#pragma unroll
    for (int j = 0; j < 2; j++)
        wmma::store_matrix_sync(
            g_pvp + ((size_t)(split * NBG + bg) * 64 + wr4 * 16) * HD + wc4 * 32 + j * 16,
            acc_o[j], HD, wmma::mem_row_major);
    if (tid < 64)
        g_rsum[(size_t)(split * NBG + bg) * 64 + tid] = rowsum[tid];
}

// ---------------- combine splits, normalize, remap -----------------------------
__global__ void flash_combine_kernel()
{
    int t = blockIdx.x * 256 + threadIdx.x;
    int rowg = t >> 5;
    int c4 = (t & 31) << 2;
    float4 s = make_float4(0.f, 0.f, 0.f, 0.f);
    float den = 0.f;
#pragma unroll
    for (int sp = 0; sp < NSPLIT; sp++) {
        float4 v = *(const float4*)(g_pvp + ((size_t)sp * NBG * 64 + rowg) * HD + c4);
        s.x += v.x; s.y += v.y; s.z += v.z; s.w += v.w;
        den += g_rsum[(size_t)sp * NBG * 64 + rowg];
    }
    float inv = 1.f / den;
    s.x *= inv; s.y *= inv; s.z *= inv; s.w *= inv;
    int bg = rowg >> 6, qr = rowg & 63;
    int b = bg >> 3, g = bg & 7, r = qr >> 4, sq = qr & 15;
    *(float4*)(g_att + (size_t)(b * 16 + sq) * DIM + (g * 4 + r) * HD + c4) = s;
}

// ---------------- kernel 4: O projection split-K(8), 512 thr -------------------
__global__ void __launch_bounds__(NTHR) o_kernel(const float* __restrict__ Wo)
{
    const int n0 = blockIdx.x * 128;
    const int kb = blockIdx.y * (DIM / SPLITO);
    const float* Abase = g_att + kb;
    const float* Bbase = Wo + (size_t)kb * DIM + n0;
    float* Cpart = g_op + (size_t)blockIdx.y * TOK * DIM + n0;
    GEMM_BODY(Abase, DIM, Bbase, DIM, Cpart, DIM, DIM / SPLITO / 32)
}

__global__ void o_reduce_kernel(float* __restrict__ out, const float* __restrict__ bo)
{
    int i4 = (blockIdx.x * 256 + threadIdx.x) * 4;
    int n = i4 & (DIM - 1);
    float4 s = *(const float4*)(bo + n);
#pragma unroll
    for (int sp = 0; sp < SPLITO; sp++) {
        float4 v = *(const float4*)(g_op + (size_t)sp * TOK * DIM + i4);
        s.x += v.x; s.y += v.y; s.z += v.z; s.w += v.w;
    }
    *(float4*)(out + i4) = s;
}

// ---------------- launch ---------------------------------------------------------
extern "C" void kernel_launch(void* const* d_in, const int* in_sizes, int n_in,
                              void* d_out, int out_size)
{
    const float* x  = (const float*)d_in[0];
    const float* kc = (const float*)d_in[1];
    const float* vc = (const float*)d_in[2];
    const float* Wq = (const float*)d_in[3];  const float* bq = (const float*)d_in[4];
    const float* Wk = (const float*)d_in[5];  const float* bk = (const float*)d_in[6];
    const float* Wv = (const float*)d_in[7];  const float* bv = (const float*)d_in[8];
    const float* Wo = (const float*)d_in[9];  const float* bo = (const float*)d_in[10];
    float* out = (float*)d_out;

    cudaFuncSetAttribute(flash_kernel,
                         cudaFuncAttributeMaxDynamicSharedMemorySize, SMEM_FLASH);
    cudaFuncSetAttribute(qkv_kernel,
                         cudaFuncAttributeMaxDynamicSharedMemorySize, SMEM_GEMM);
    cudaFuncSetAttribute(o_kernel,
                         cudaFuncAttributeMaxDynamicSharedMemorySize, SMEM_GEMM);

    qkv_kernel<<<dim3(48, SPLITQ), NTHR, SMEM_GEMM>>>(x, Wq, Wk, Wv);
    qkv_reduce_kernel<<<TOK * QKV_N / 1024, 256>>>();
    flash_kernel<<<dim3(NSPLIT, NBG), NTHR, SMEM_FLASH>>>(kc, vc, bq, bk, bv);
    flash_combine_kernel<<<512, 256>>>();
    o_kernel<<<dim3(32, SPLITO), NTHR, SMEM_GEMM>>>(Wo);
    o_reduce_kernel<<<512, 256>>>(out, bo);
}

// round 9
// speedup vs baseline: 1.8590x; 1.0009x over previous
#include <cuda_runtime.h>
#include <cuda_bf16.h>
#include <mma.h>
#include <math.h>

using namespace nvcuda;

#define BSZ     8
#define QL      16
#define TOK     128
#define DIM     4096
#define NKV     8
#define HD      128
#define MAXSEQ  4096
#define STARTP  4080
#define KVLEN   4096
#define QKV_N   6144
#define NBG     64
#define NSPLIT  4
#define KVSPLIT 1024
#define LT      64
#define NT_FL   (KVSPLIT / LT)
#define SPLITQ  8
#define SPLITO  8
#define NTHR    512

__device__ float g_qkv[TOK * QKV_N];
__device__ float g_qkvp[SPLITQ * TOK * QKV_N];
__device__ float g_op[SPLITO * TOK * DIM];
__device__ float g_pvp[NSPLIT * NBG * 64 * HD];
__device__ float g_rsum[NSPLIT * NBG * 64];
__device__ float g_att[TOK * DIM];

__device__ __forceinline__ float tf32r(float x) { return wmma::__float_to_tf32(x); }

typedef wmma::fragment<wmma::accumulator, 16, 16, 8, float> FragC;
typedef wmma::fragment<wmma::matrix_a, 16, 16, 8, wmma::precision::tf32, wmma::row_major> FragA;
typedef wmma::fragment<wmma::matrix_b, 16, 16, 8, wmma::precision::tf32, wmma::row_major> FragB;
typedef wmma::fragment<wmma::matrix_b, 16, 16, 8, wmma::precision::tf32, wmma::col_major> FragBT;

// ---------------- 128x128 split-K GEMM body, 512 thr, warp tile 32x32 ----------
#define SMEM_GEMM ((2 * 128 * 36 + 2 * 32 * 132) * 4)

#define GEMM_BODY(Abase, LDAG, Bbase, LDBG, CPART, LDC, NCHUNK)                    \
    extern __shared__ float smg[];                                                 \
    float* Asb[2] = {smg, smg + 128 * 36};                                         \
    float* Bsb[2] = {smg + 2 * 128 * 36, smg + 2 * 128 * 36 + 32 * 132};           \
    const int tid = threadIdx.x;                                                   \
    const int wid = tid >> 5, wr = wid >> 2, wcx = wid & 3;                        \
    const int amr0 = tid >> 3, akc = (tid & 7) << 2;                               \
    const int bkr0 = tid >> 5, bnc = (tid & 31) << 2;                              \
    FragC acc[2][2];                                                               \
    _Pragma("unroll")                                                              \
    for (int i = 0; i < 2; i++)                                                    \
        _Pragma("unroll")                                                          \
        for (int j = 0; j < 2; j++) wmma::fill_fragment(acc[i][j], 0.0f);          \
    float4 ra[2], rb[2];                                                           \
    _Pragma("unroll")                                                              \
    for (int i = 0; i < 2; i++)                                                    \
        ra[i] = *(const float4*)((Abase) + (size_t)(amr0 + 64 * i) * (LDAG) + akc); \
    _Pragma("unroll")                                                              \
    for (int i = 0; i < 2; i++)                                                    \
        rb[i] = *(const float4*)((Bbase) + (size_t)(bkr0 + 16 * i) * (LDBG) + bnc); \
    _Pragma("unroll")                                                              \
    for (int i = 0; i < 2; i++) {                                                  \
        float4 c = ra[i];                                                          \
        c.x = tf32r(c.x); c.y = tf32r(c.y); c.z = tf32r(c.z); c.w = tf32r(c.w);    \
        *(float4*)(&Asb[0][(amr0 + 64 * i) * 36 + akc]) = c;                       \
    }                                                                              \
    _Pragma("unroll")                                                              \
    for (int i = 0; i < 2; i++) {                                                  \
        float4 c = rb[i];                                                          \
        c.x = tf32r(c.x); c.y = tf32r(c.y); c.z = tf32r(c.z); c.w = tf32r(c.w);    \
        *(float4*)(&Bsb[0][(bkr0 + 16 * i) * 132 + bnc]) = c;                      \
    }                                                                              \
    __syncthreads();                                                               \
    for (int t = 0; t < (NCHUNK); t++) {                                           \
        int cur = t & 1;                                                           \
        if (t + 1 < (NCHUNK)) {                                                    \
            _Pragma("unroll")                                                      \
            for (int i = 0; i < 2; i++)                                            \
                ra[i] = *(const float4*)((Abase) + (size_t)(amr0 + 64 * i) * (LDAG) + (t + 1) * 32 + akc); \
            _Pragma("unroll")                                                      \
            for (int i = 0; i < 2; i++)                                            \
                rb[i] = *(const float4*)((Bbase) + (size_t)((t + 1) * 32 + bkr0 + 16 * i) * (LDBG) + bnc); \
        }                                                                          \
        _Pragma("unroll")                                                          \
        for (int kk = 0; kk < 32; kk += 8) {                                       \
            FragA a[2]; FragB b[2];                                                \
            _Pragma("unroll")                                                      \
            for (int i = 0; i < 2; i++)                                            \
                wmma::load_matrix_sync(a[i], Asb[cur] + (wr * 32 + i * 16) * 36 + kk, 36); \
            _Pragma("unroll")                                                      \
            for (int j = 0; j < 2; j++)                                            \
                wmma::load_matrix_sync(b[j], Bsb[cur] + kk * 132 + wcx * 32 + j * 16, 132); \
            _Pragma("unroll")                                                      \
            for (int i = 0; i < 2; i++)                                            \
                _Pragma("unroll")                                                  \
                for (int j = 0; j < 2; j++)                                        \
                    wmma::mma_sync(acc[i][j], a[i], b[j], acc[i][j]);              \
        }                                                                          \
        if (t + 1 < (NCHUNK)) {                                                    \
            _Pragma("unroll")                                                      \
            for (int i = 0; i < 2; i++) {                                          \
                float4 c = ra[i];                                                  \
                c.x = tf32r(c.x); c.y = tf32r(c.y); c.z = tf32r(c.z); c.w = tf32r(c.w); \
                *(float4*)(&Asb[1 - cur][(amr0 + 64 * i) * 36 + akc]) = c;         \
            }                                                                      \
            _Pragma("unroll")                                                      \
            for (int i = 0; i < 2; i++) {                                          \
                float4 c = rb[i];                                                  \
                c.x = tf32r(c.x); c.y = tf32r(c.y); c.z = tf32r(c.z); c.w = tf32r(c.w); \
                *(float4*)(&Bsb[1 - cur][(bkr0 + 16 * i) * 132 + bnc]) = c;        \
            }                                                                      \
        }                                                                          \
        __syncthreads();                                                           \
    }                                                                              \
    _Pragma("unroll")                                                              \
    for (int i = 0; i < 2; i++)                                                    \
        _Pragma("unroll")                                                          \
        for (int j = 0; j < 2; j++)                                                \
            wmma::store_matrix_sync((CPART) + (size_t)(wr * 32 + i * 16) * (LDC) + wcx * 32 + j * 16, \
                                    acc[i][j], (LDC), wmma::mem_row_major);

// ---------------- kernel 1: QKV GEMM split-K(8), 512 thr -----------------------
__global__ void __launch_bounds__(NTHR) qkv_kernel(
    const float* __restrict__ x,
    const float* __restrict__ Wq, const float* __restrict__ Wk,
    const float* __restrict__ Wv)
{
    const int n0 = blockIdx.x * 128;
    const int kb = blockIdx.y * (DIM / SPLITQ);
    const float* B; int ldb, col;
    if (n0 < 4096)      { B = Wq; ldb = 4096; col = n0; }
    else if (n0 < 5120) { B = Wk; ldb = 1024; col = n0 - 4096; }
    else                { B = Wv; ldb = 1024; col = n0 - 5120; }

    const float* Abase = x + kb;
    const float* Bbase = B + (size_t)kb * ldb + col;
    float* Cpart = g_qkvp + (size_t)blockIdx.y * TOK * QKV_N + n0;
    GEMM_BODY(Abase, DIM, Bbase, ldb, Cpart, QKV_N, DIM / SPLITQ / 32)
}

__global__ void qkv_reduce_kernel()
{
    int i4 = (blockIdx.x * 256 + threadIdx.x) * 4;
    float4 s = make_float4(0.f, 0.f, 0.f, 0.f);
#pragma unroll
    for (int sp = 0; sp < SPLITQ; sp++) {
        float4 v = *(const float4*)(g_qkvp + (size_t)sp * TOK * QKV_N + i4);
        s.x += v.x; s.y += v.y; s.z += v.z; s.w += v.w;
    }
    *(float4*)(g_qkv + i4) = s;
}

// ---------------- kernel 2: flash attention, LT=64, 2 CTAs/SM ------------------
// smem: Qs[64*132], KVs[64*136], Ss[64*72], rowsum[64], tmp[512]  = ~89 KB
#define SMEM_FLASH ((64 * 132 + 64 * 136 + 64 * 72 + 64 + 512) * 4)

__global__ void __launch_bounds__(NTHR, 2) flash_kernel(
    const float* __restrict__ k_cache, const float* __restrict__ v_cache,
    const float* __restrict__ bq, const float* __restrict__ bk,
    const float* __restrict__ bv)
{
    extern __shared__ float sm[];
    float* Qs     = sm;                      // [64][132]
    float* KVs    = Qs + 64 * 132;           // [64][136]
    float* Ss     = KVs + 64 * 136;          // [64][72]
    float* rowsum = Ss + 64 * 72;            // [64]
    float* tmp    = rowsum + 64;             // [8][64]

    const int split = blockIdx.x;
    const int bg = blockIdx.y, b = bg >> 3, g = bg & 7;
    const int tid = threadIdx.x, wid = tid >> 5;
    const int wr4 = wid >> 2, wc4 = wid & 3;   // 4x4 warp grid
    const float scale = 0.08838834764831845f;

    const int lr0 = tid >> 5;                  // 0..15
    const int d4  = (tid & 31) << 2;

    // Q staging: 64 x 128
#pragma unroll
    for (int i = 0; i < 4; i++) {
        int m = lr0 + 16 * i;
        int r = m >> 4, s = m & 15;
        int hcol = (g * 4 + r) * HD + d4;
        float4 q = *(const float4*)(g_qkv + (size_t)(b * 16 + s) * QKV_N + hcol);
        float4 bb = *(const float4*)(bq + hcol);
        float4 o;
        o.x = tf32r((q.x + bb.x) * scale); o.y = tf32r((q.y + bb.y) * scale);
        o.z = tf32r((q.z + bb.z) * scale); o.w = tf32r((q.w + bb.w) * scale);
        *(float4*)(Qs + m * 132 + d4) = o;
    }
    if (tid < 64) rowsum[tid] = 0.f;

    FragC acc_o[2];
#pragma unroll
    for (int j = 0; j < 2; j++) wmma::fill_fragment(acc_o[j], 0.0f);

    const int row = tid & 63, qq = tid >> 6;   // exp: 8 chunks of 8 cols

    // direct KV staging (no reg prefetch; co-resident CTA hides latency)
#define STAGE_KV(l0, qoff, cache, bias)                                            \
    _Pragma("unroll")                                                              \
    for (int i = 0; i < 4; i++) {                                                  \
        int l = lr0 + 16 * i;                                                      \
        int lg = (l0) + l;                                                         \
        float4 c;                                                                  \
        if (lg >= STARTP) {                                                        \
            c = *(const float4*)(g_qkv + (size_t)(b * 16 + (lg - STARTP)) * QKV_N  \
                                 + (qoff) + g * HD + d4);                          \
            float4 bb = *(const float4*)((bias) + g * HD + d4);                    \
            c.x += bb.x; c.y += bb.y; c.z += bb.z; c.w += bb.w;                    \
        } else {                                                                   \
            c = *(const float4*)((cache) + (((size_t)b * MAXSEQ + lg) * NKV + g) * HD + d4); \
        }                                                                          \
        c.x = tf32r(c.x); c.y = tf32r(c.y); c.z = tf32r(c.z); c.w = tf32r(c.w);    \
        *(float4*)(KVs + l * 136 + d4) = c;                                        \
    }

    const int lbase0 = split * KVSPLIT;

    for (int t = 0; t < NT_FL; t++) {
        const int l0 = lbase0 + t * LT;

        STAGE_KV(l0, 4096, k_cache, bk)
        __syncthreads();

        // S = Q @ K^T : 64x64, k=128; warp tile 16x16
        FragC acc_s;
        wmma::fill_fragment(acc_s, 0.0f);
#pragma unroll
        for (int kk = 0; kk < HD; kk += 8) {
            FragA a; FragBT bt;
            wmma::load_matrix_sync(a, Qs + (wr4 * 16) * 132 + kk, 132);
            wmma::load_matrix_sync(bt, KVs + (wc4 * 16) * 136 + kk, 136);
            wmma::mma_sync(acc_s, a, bt, acc_s);
        }
        __syncthreads();                      // KVs reads (S) done before V overwrites
        wmma::store_matrix_sync(Ss + (wr4 * 16) * 72 + wc4 * 16, acc_s, 72,
                                wmma::mem_row_major);
        __syncthreads();

        STAGE_KV(l0, 5120, v_cache, bv)       // V into KVs
        {
            float part = 0.f;
            float* sp = Ss + row * 72 + qq * 8;
#pragma unroll
            for (int j = 0; j < 8; j++) {
                float e = tf32r(__expf(sp[j]));
                sp[j] = e;
                part += e;
            }
            tmp[qq * 64 + row] = part;
        }
        __syncthreads();

        if (tid < 64) {
            float s = 0.f;
#pragma unroll
            for (int q8 = 0; q8 < 8; q8++) s += tmp[q8 * 64 + tid];
            rowsum[tid] += s;
        }

        // O += P @ V : 64x128, k=64; warp tile 16x32
#pragma unroll
        for (int kk = 0; kk < LT; kk += 8) {
            FragA a;
            wmma::load_matrix_sync(a, Ss + (wr4 * 16) * 72 + kk, 72);
#pragma unroll
            for (int j = 0; j < 2; j++) {
                FragB bfr;
                wmma::load_matrix_sync(bfr, KVs + kk * 136 + wc4 * 32 + j * 16, 136);
                wmma::mma_sync(acc_o[j], a, bfr, acc_o[j]);
            }
        }
        __syncthreads();
    }

#pragma unroll
    for (int j = 0; j < 2; j++)
        wmma::store_matrix_sync(
            g_pvp + ((size_t)(split * NBG + bg) * 64 + wr4 * 16) * HD + wc4 * 32 + j * 16,
            acc_o[j], HD, wmma::mem_row_major);
    if (tid < 64)
        g_rsum[(size_t)(split * NBG + bg) * 64 + tid] = rowsum[tid];
}

// ---------------- combine splits, normalize, remap -----------------------------
__global__ void flash_combine_kernel()
{
    int t = blockIdx.x * 256 + threadIdx.x;
    int rowg = t >> 5;
    int c4 = (t & 31) << 2;
    float4 s = make_float4(0.f, 0.f, 0.f, 0.f);
    float den = 0.f;
#pragma unroll
    for (int sp = 0; sp < NSPLIT; sp++) {
        float4 v = *(const float4*)(g_pvp + ((size_t)sp * NBG * 64 + rowg) * HD + c4);
        s.x += v.x; s.y += v.y; s.z += v.z; s.w += v.w;
        den += g_rsum[(size_t)sp * NBG * 64 + rowg];
    }
    float inv = 1.f / den;
    s.x *= inv; s.y *= inv; s.z *= inv; s.w *= inv;
    int bg = rowg >> 6, qr = rowg & 63;
    int b = bg >> 3, g = bg & 7, r = qr >> 4, sq = qr & 15;
    *(float4*)(g_att + (size_t)(b * 16 + sq) * DIM + (g * 4 + r) * HD + c4) = s;
}

// ---------------- kernel 4: O projection split-K(8), 512 thr -------------------
__global__ void __launch_bounds__(NTHR) o_kernel(const float* __restrict__ Wo)
{
    const int n0 = blockIdx.x * 128;
    const int kb = blockIdx.y * (DIM / SPLITO);
    const float* Abase = g_att + kb;
    const float* Bbase = Wo + (size_t)kb * DIM + n0;
    float* Cpart = g_op + (size_t)blockIdx.y * TOK * DIM + n0;
    GEMM_BODY(Abase, DIM, Bbase, DIM, Cpart, DIM, DIM / SPLITO / 32)
}

__global__ void o_reduce_kernel(float* __restrict__ out, const float* __restrict__ bo)
{
    int i4 = (blockIdx.x * 256 + threadIdx.x) * 4;
    int n = i4 & (DIM - 1);
    float4 s = *(const float4*)(bo + n);
#pragma unroll
    for (int sp = 0; sp < SPLITO; sp++) {
        float4 v = *(const float4*)(g_op + (size_t)sp * TOK * DIM + i4);
        s.x += v.x; s.y += v.y; s.z += v.z; s.w += v.w;
    }
    *(float4*)(out + i4) = s;
}

// ---------------- launch ---------------------------------------------------------
extern "C" void kernel_launch(void* const* d_in, const int* in_sizes, int n_in,
                              void* d_out, int out_size)
{
    const float* x  = (const float*)d_in[0];
    const float* kc = (const float*)d_in[1];
    const float* vc = (const float*)d_in[2];
    const float* Wq = (const float*)d_in[3];  const float* bq = (const float*)d_in[4];
    const float* Wk = (const float*)d_in[5];  const float* bk = (const float*)d_in[6];
    const float* Wv = (const float*)d_in[7];  const float* bv = (const float*)d_in[8];
    const float* Wo = (const float*)d_in[9];  const float* bo = (const float*)d_in[10];
    float* out = (float*)d_out;

    cudaFuncSetAttribute(flash_kernel,
                         cudaFuncAttributeMaxDynamicSharedMemorySize, SMEM_FLASH);
    cudaFuncSetAttribute(qkv_kernel,
                         cudaFuncAttributeMaxDynamicSharedMemorySize, SMEM_GEMM);
    cudaFuncSetAttribute(o_kernel,
                         cudaFuncAttributeMaxDynamicSharedMemorySize, SMEM_GEMM);

    qkv_kernel<<<dim3(48, SPLITQ), NTHR, SMEM_GEMM>>>(x, Wq, Wk, Wv);
    qkv_reduce_kernel<<<TOK * QKV_N / 1024, 256>>>();
    flash_kernel<<<dim3(NSPLIT, NBG), NTHR, SMEM_FLASH>>>(kc, vc, bq, bk, bv);
    flash_combine_kernel<<<512, 256>>>();
    o_kernel<<<dim3(32, SPLITO), NTHR, SMEM_GEMM>>>(Wo);
    o_reduce_kernel<<<512, 256>>>(out, bo);
}

// round 10
// speedup vs baseline: 3.6960x; 1.9882x over previous
#include <cuda_runtime.h>
#include <cuda_fp16.h>
#include <mma.h>
#include <math.h>
#include <cstdint>

using namespace nvcuda;

#define BSZ     8
#define QL      16
#define TOK     128
#define DIM     4096
#define NKV     8
#define HD      128
#define MAXSEQ  4096
#define STARTP  4080
#define KVLEN   4096
#define QKV_N   6144
#define NBG     64
#define NSPLIT  4
#define KVSPLIT 1024
#define LT      64
#define NT_FL   (KVSPLIT / LT)
#define SPLITQ  8
#define SPLITO  8
#define NTHR    512

__device__ float g_qkv[TOK * QKV_N];
__device__ float g_qkvp[SPLITQ * TOK * QKV_N];
__device__ float g_op[SPLITO * TOK * DIM];
__device__ float g_pvp[NSPLIT * NBG * 64 * HD];
__device__ float g_rsum[NSPLIT * NBG * 64];
__device__ float g_att[TOK * DIM];

typedef wmma::fragment<wmma::accumulator, 16, 16, 16, float> HC;
typedef wmma::fragment<wmma::matrix_a, 16, 16, 16, __half, wmma::row_major> HA;
typedef wmma::fragment<wmma::matrix_b, 16, 16, 16, __half, wmma::row_major> HB;
typedef wmma::fragment<wmma::matrix_b, 16, 16, 16, __half, wmma::col_major> HBT;

// 8 fp32 -> 8 half packed in uint4
__device__ __forceinline__ uint4 f8h8(float4 a, float4 b) {
    __half2 h0 = __floats2half2_rn(a.x, a.y);
    __half2 h1 = __floats2half2_rn(a.z, a.w);
    __half2 h2 = __floats2half2_rn(b.x, b.y);
    __half2 h3 = __floats2half2_rn(b.z, b.w);
    uint4 r;
    r.x = *(uint32_t*)&h0; r.y = *(uint32_t*)&h1;
    r.z = *(uint32_t*)&h2; r.w = *(uint32_t*)&h3;
    return r;
}

// ---------------- 128x128 split-K fp16 GEMM body, 512 thr, warp 32x32 ----------
// smem (bytes): As 2*128*40*2 + Bs 2*32*136*2 = 37888
#define SMEM_GEMM (2 * 128 * 40 * 2 + 2 * 32 * 136 * 2)

#define GEMM_BODY(Abase, LDAG, Bbase, LDBG, CPART, LDC, NCHUNK)                    \
    extern __shared__ __half smg[];                                                \
    __half* Asb[2] = {smg, smg + 128 * 40};                                        \
    __half* Bsb[2] = {smg + 2 * 128 * 40, smg + 2 * 128 * 40 + 32 * 136};          \
    const int tid = threadIdx.x;                                                   \
    const int wid = tid >> 5, wr = wid >> 2, wcx = wid & 3;                        \
    const int am = tid >> 2, ak = (tid & 3) << 3;   /* A: 128 x 32 */              \
    const int bk = tid >> 4, bn = (tid & 15) << 3;  /* B: 32 x 128 */              \
    HC acc[2][2];                                                                  \
    _Pragma("unroll")                                                              \
    for (int i = 0; i < 2; i++)                                                    \
        _Pragma("unroll")                                                          \
        for (int j = 0; j < 2; j++) wmma::fill_fragment(acc[i][j], 0.0f);          \
    float4 ra0, ra1, rb0, rb1;                                                     \
    ra0 = *(const float4*)((Abase) + (size_t)am * (LDAG) + ak);                    \
    ra1 = *(const float4*)((Abase) + (size_t)am * (LDAG) + ak + 4);                \
    rb0 = *(const float4*)((Bbase) + (size_t)bk * (LDBG) + bn);                    \
    rb1 = *(const float4*)((Bbase) + (size_t)bk * (LDBG) + bn + 4);                \
    *(uint4*)(&Asb[0][am * 40 + ak]) = f8h8(ra0, ra1);                             \
    *(uint4*)(&Bsb[0][bk * 136 + bn]) = f8h8(rb0, rb1);                            \
    __syncthreads();                                                               \
    for (int t = 0; t < (NCHUNK); t++) {                                           \
        int cur = t & 1;                                                           \
        if (t + 1 < (NCHUNK)) {                                                    \
            ra0 = *(const float4*)((Abase) + (size_t)am * (LDAG) + (t + 1) * 32 + ak); \
            ra1 = *(const float4*)((Abase) + (size_t)am * (LDAG) + (t + 1) * 32 + ak + 4); \
            rb0 = *(const float4*)((Bbase) + (size_t)((t + 1) * 32 + bk) * (LDBG) + bn); \
            rb1 = *(const float4*)((Bbase) + (size_t)((t + 1) * 32 + bk) * (LDBG) + bn + 4); \
        }                                                                          \
        _Pragma("unroll")                                                          \
        for (int kk = 0; kk < 32; kk += 16) {                                      \
            HA a[2]; HB b[2];                                                      \
            _Pragma("unroll")                                                      \
            for (int i = 0; i < 2; i++)                                            \
                wmma::load_matrix_sync(a[i], Asb[cur] + (wr * 32 + i * 16) * 40 + kk, 40); \
            _Pragma("unroll")                                                      \
            for (int j = 0; j < 2; j++)                                            \
                wmma::load_matrix_sync(b[j], Bsb[cur] + kk * 136 + wcx * 32 + j * 16, 136); \
            _Pragma("unroll")                                                      \
            for (int i = 0; i < 2; i++)                                            \
                _Pragma("unroll")                                                  \
                for (int j = 0; j < 2; j++)                                        \
                    wmma::mma_sync(acc[i][j], a[i], b[j], acc[i][j]);              \
        }                                                                          \
        if (t + 1 < (NCHUNK)) {                                                    \
            *(uint4*)(&Asb[1 - cur][am * 40 + ak]) = f8h8(ra0, ra1);               \
            *(uint4*)(&Bsb[1 - cur][bk * 136 + bn]) = f8h8(rb0, rb1);              \
        }                                                                          \
        __syncthreads();                                                           \
    }                                                                              \
    _Pragma("unroll")                                                              \
    for (int i = 0; i < 2; i++)                                                    \
        _Pragma("unroll")                                                          \
        for (int j = 0; j < 2; j++)                                                \
            wmma::store_matrix_sync((CPART) + (size_t)(wr * 32 + i * 16) * (LDC) + wcx * 32 + j * 16, \
                                    acc[i][j], (LDC), wmma::mem_row_major);

// ---------------- kernel 1: QKV GEMM split-K(8) --------------------------------
__global__ void __launch_bounds__(NTHR) qkv_kernel(
    const float* __restrict__ x,
    const float* __restrict__ Wq, const float* __restrict__ Wk,
    const float* __restrict__ Wv)
{
    const int n0 = blockIdx.x * 128;
    const int kb = blockIdx.y * (DIM / SPLITQ);
    const float* B; int ldb, col;
    if (n0 < 4096)      { B = Wq; ldb = 4096; col = n0; }
    else if (n0 < 5120) { B = Wk; ldb = 1024; col = n0 - 4096; }
    else                { B = Wv; ldb = 1024; col = n0 - 5120; }

    const float* Abase = x + kb;
    const float* Bbase = B + (size_t)kb * ldb + col;
    float* Cpart = g_qkvp + (size_t)blockIdx.y * TOK * QKV_N + n0;
    GEMM_BODY(Abase, DIM, Bbase, ldb, Cpart, QKV_N, DIM / SPLITQ / 32)
}

__global__ void qkv_reduce_kernel()
{
    int i4 = (blockIdx.x * 256 + threadIdx.x) * 4;
    float4 s = make_float4(0.f, 0.f, 0.f, 0.f);
#pragma unroll
    for (int sp = 0; sp < SPLITQ; sp++) {
        float4 v = *(const float4*)(g_qkvp + (size_t)sp * TOK * QKV_N + i4);
        s.x += v.x; s.y += v.y; s.z += v.z; s.w += v.w;
    }
    *(float4*)(g_qkv + i4) = s;
}

// ---------------- kernel 2: flash attention, fp16 MMA ---------------------------
// smem bytes: Qs 64*136*2 + KVs 64*136*2 + Ssf 64*72*4 + Ps 64*72*2 + (64+512)*4
#define SMEM_FLASH (64*136*2 + 64*136*2 + 64*72*4 + 64*72*2 + (64 + 512) * 4)

__global__ void __launch_bounds__(NTHR, 2) flash_kernel(
    const float* __restrict__ k_cache, const float* __restrict__ v_cache,
    const float* __restrict__ bq, const float* __restrict__ bk,
    const float* __restrict__ bv)
{
    extern __shared__ char smc[];
    __half* Qs   = (__half*)smc;                          // [64][136]
    __half* KVs  = Qs + 64 * 136;                         // [64][136]
    __half* Ps   = KVs + 64 * 136;                        // [64][72]
    float* Ssf   = (float*)(Ps + 64 * 72);                // [64][72]
    float* rowsum = Ssf + 64 * 72;                        // [64]
    float* tmp    = rowsum + 64;                          // [8][64]

    const int split = blockIdx.x;
    const int bg = blockIdx.y, b = bg >> 3, g = bg & 7;
    const int tid = threadIdx.x, wid = tid >> 5;
    const int wr4 = wid >> 2, wc4 = wid & 3;   // 4x4 warp grid
    const float scale = 0.08838834764831845f;

    // staging map: 64 rows x 16 col-groups of 8; 1024 slots, 2 per thread
    const int sm0 = tid >> 4;                 // row  (i=0) .. +32 (i=1)
    const int sc8 = (tid & 15) << 3;          // col8

    // Q staging: 64 x 128, bias+scale, fp32 -> half
#pragma unroll
    for (int i = 0; i < 2; i++) {
        int m = sm0 + 32 * i;
        int r = m >> 4, s = m & 15;
        int hcol = (g * 4 + r) * HD + sc8;
        const float* qp = g_qkv + (size_t)(b * 16 + s) * QKV_N + hcol;
        float4 q0 = *(const float4*)(qp);
        float4 q1 = *(const float4*)(qp + 4);
        float4 b0 = *(const float4*)(bq + hcol);
        float4 b1 = *(const float4*)(bq + hcol + 4);
        q0.x = (q0.x + b0.x) * scale; q0.y = (q0.y + b0.y) * scale;
        q0.z = (q0.z + b0.z) * scale; q0.w = (q0.w + b0.w) * scale;
        q1.x = (q1.x + b1.x) * scale; q1.y = (q1.y + b1.y) * scale;
        q1.z = (q1.z + b1.z) * scale; q1.w = (q1.w + b1.w) * scale;
        *(uint4*)(&Qs[m * 136 + sc8]) = f8h8(q0, q1);
    }
    if (tid < 64) rowsum[tid] = 0.f;

    HC acc_o[2];
#pragma unroll
    for (int j = 0; j < 2; j++) wmma::fill_fragment(acc_o[j], 0.0f);

    const int row = tid & 63, qq = tid >> 6;   // exp: 8 chunks of 8 cols

#define STAGE_KV(l0, qoff, cache, bias)                                            \
    _Pragma("unroll")                                                              \
    for (int i = 0; i < 2; i++) {                                                  \
        int l = sm0 + 32 * i;                                                      \
        int lg = (l0) + l;                                                         \
        float4 c0, c1;                                                             \
        if (lg >= STARTP) {                                                        \
            const float* sp_ = g_qkv + (size_t)(b * 16 + (lg - STARTP)) * QKV_N    \
                               + (qoff) + g * HD + sc8;                            \
            c0 = *(const float4*)(sp_); c1 = *(const float4*)(sp_ + 4);            \
            float4 b0 = *(const float4*)((bias) + g * HD + sc8);                   \
            float4 b1 = *(const float4*)((bias) + g * HD + sc8 + 4);               \
            c0.x += b0.x; c0.y += b0.y; c0.z += b0.z; c0.w += b0.w;                \
            c1.x += b1.x; c1.y += b1.y; c1.z += b1.z; c1.w += b1.w;                \
        } else {                                                                   \
            const float* sp_ = (cache) + (((size_t)b * MAXSEQ + lg) * NKV + g) * HD + sc8; \
            c0 = *(const float4*)(sp_); c1 = *(const float4*)(sp_ + 4);            \
        }                                                                          \
        *(uint4*)(&KVs[l * 136 + sc8]) = f8h8(c0, c1);                             \
    }

    const int lbase0 = split * KVSPLIT;

    for (int t = 0; t < NT_FL; t++) {
        const int l0 = lbase0 + t * LT;

        STAGE_KV(l0, 4096, k_cache, bk)
        __syncthreads();

        // S = Q @ K^T : 64x64, k=128 in 8 steps of 16; warp tile 16x16
        HC acc_s;
        wmma::fill_fragment(acc_s, 0.0f);
#pragma unroll
        for (int kk = 0; kk < HD; kk += 16) {
            HA a; HBT bt;
            wmma::load_matrix_sync(a, Qs + (wr4 * 16) * 136 + kk, 136);
            wmma::load_matrix_sync(bt, KVs + (wc4 * 16) * 136 + kk, 136);
            wmma::mma_sync(acc_s, a, bt, acc_s);
        }
        wmma::store_matrix_sync(Ssf + (wr4 * 16) * 72 + wc4 * 16, acc_s, 72,
                                wmma::mem_row_major);
        __syncthreads();   // S reads of KVs done; Ssf written

        STAGE_KV(l0, 5120, v_cache, bv)       // V into KVs
        {
            float* sp = Ssf + row * 72 + qq * 8;
            float e[8];
            float part = 0.f;
#pragma unroll
            for (int j = 0; j < 8; j++) {
                e[j] = __expf(sp[j]);
                part += e[j];
            }
            tmp[qq * 64 + row] = part;
            float4 e0 = {e[0], e[1], e[2], e[3]};
            float4 e1 = {e[4], e[5], e[6], e[7]};
            *(uint4*)(&Ps[row * 72 + qq * 8]) = f8h8(e0, e1);
        }
        __syncthreads();

        if (tid < 64) {
            float s = 0.f;
#pragma unroll
            for (int q8 = 0; q8 < 8; q8++) s += tmp[q8 * 64 + tid];
            rowsum[tid] += s;
        }

        // O += P @ V : 64x128, k=64 in 4 steps of 16; warp tile 16x32
#pragma unroll
        for (int kk = 0; kk < LT; kk += 16) {
            HA a;
            wmma::load_matrix_sync(a, Ps + (wr4 * 16) * 72 + kk, 72);
#pragma unroll
            for (int j = 0; j < 2; j++) {
                HB bfr;
                wmma::load_matrix_sync(bfr, KVs + kk * 136 + wc4 * 32 + j * 16, 136);
                wmma::mma_sync(acc_o[j], a, bfr, acc_o[j]);
            }
        }
        __syncthreads();
    }

#pragma unroll
    for (int j = 0; j < 2; j++)
        wmma::store_matrix_sync(
            g_pvp + ((size_t)(split * NBG + bg) * 64 + wr4 * 16) * HD + wc4 * 32 + j * 16,
            acc_o[j], HD, wmma::mem_row_major);
    if (tid < 64)
        g_rsum[(size_t)(split * NBG + bg) * 64 + tid] = rowsum[tid];
}

// ---------------- combine splits, normalize, remap -----------------------------
__global__ void flash_combine_kernel()
{
    int t = blockIdx.x * 256 + threadIdx.x;
    int rowg = t >> 5;
    int c4 = (t & 31) << 2;
    float4 s = make_float4(0.f, 0.f, 0.f, 0.f);
    float den = 0.f;
#pragma unroll
    for (int sp = 0; sp < NSPLIT; sp++) {
        float4 v = *(const float4*)(g_pvp + ((size_t)sp * NBG * 64 + rowg) * HD + c4);
        s.x += v.x; s.y += v.y; s.z += v.z; s.w += v.w;
        den += g_rsum[(size_t)sp * NBG * 64 + rowg];
    }
    float inv = 1.f / den;
    s.x *= inv; s.y *= inv; s.z *= inv; s.w *= inv;
    int bg = rowg >> 6, qr = rowg & 63;
    int b = bg >> 3, g = bg & 7, r = qr >> 4, sq = qr & 15;
    *(float4*)(g_att + (size_t)(b * 16 + sq) * DIM + (g * 4 + r) * HD + c4) = s;
}

// ---------------- kernel 4: O projection split-K(8) -----------------------------
__global__ void __launch_bounds__(NTHR) o_kernel(const float* __restrict__ Wo)
{
    const int n0 = blockIdx.x * 128;
    const int kb = blockIdx.y * (DIM / SPLITO);
    const float* Abase = g_att + kb;
    const float* Bbase = Wo + (size_t)kb * DIM + n0;
    float* Cpart = g_op + (size_t)blockIdx.y * TOK * DIM + n0;
    GEMM_BODY(Abase, DIM, Bbase, DIM, Cpart, DIM, DIM / SPLITO / 32)
}

__global__ void o_reduce_kernel(float* __restrict__ out, const float* __restrict__ bo)
{
    int i4 = (blockIdx.x * 256 + threadIdx.x) * 4;
    int n = i4 & (DIM - 1);
    float4 s = *(const float4*)(bo + n);
#pragma unroll
    for (int sp = 0; sp < SPLITO; sp++) {
        float4 v = *(const float4*)(g_op + (size_t)sp * TOK * DIM + i4);
        s.x += v.x; s.y += v.y; s.z += v.z; s.w += v.w;
    }
    *(float4*)(out + i4) = s;
}

// ---------------- launch ----------------------------------------------------------
extern "C" void kernel_launch(void* const* d_in, const int* in_sizes, int n_in,
                              void* d_out, int out_size)
{
    const float* x  = (const float*)d_in[0];
    const float* kc = (const float*)d_in[1];
    const float* vc = (const float*)d_in[2];
    const float* Wq = (const float*)d_in[3];  const float* bq = (const float*)d_in[4];
    const float* Wk = (const float*)d_in[5];  const float* bk = (const float*)d_in[6];
    const float* Wv = (const float*)d_in[7];  const float* bv = (const float*)d_in[8];
    const float* Wo = (const float*)d_in[9];  const float* bo = (const float*)d_in[10];
    float* out = (float*)d_out;

    cudaFuncSetAttribute(flash_kernel,
                         cudaFuncAttributeMaxDynamicSharedMemorySize, SMEM_FLASH);
    cudaFuncSetAttribute(qkv_kernel,
                         cudaFuncAttributeMaxDynamicSharedMemorySize, SMEM_GEMM);
    cudaFuncSetAttribute(o_kernel,
                         cudaFuncAttributeMaxDynamicSharedMemorySize, SMEM_GEMM);

    qkv_kernel<<<dim3(48, SPLITQ), NTHR, SMEM_GEMM>>>(x, Wq, Wk, Wv);
    qkv_reduce_kernel<<<TOK * QKV_N / 1024, 256>>>();
    flash_kernel<<<dim3(NSPLIT, NBG), NTHR, SMEM_FLASH>>>(kc, vc, bq, bk, bv);
    flash_combine_kernel<<<512, 256>>>();
    o_kernel<<<dim3(32, SPLITO), NTHR, SMEM_GEMM>>>(Wo);
    o_reduce_kernel<<<512, 256>>>(out, bo);
}